// round 7
// baseline (speedup 1.0000x reference)
#include <cuda_runtime.h>
#include <cuda_bf16.h>
#include <math.h>
#include <stdint.h>

#define HD 128
#define NMAX 100000
#define EMAX 1600000

// ================= scratch (static device memory) =================
__device__ float g_h[(size_t)NMAX * HD];
__device__ float g_t[(size_t)NMAX * HD];
__device__ float g_s[(size_t)NMAX * HD];
__device__ float g_dinv[NMAX];
__device__ int   g_deg[NMAX];
__device__ int   g_off[NMAX];
__device__ int   g_cur[NMAX];
__device__ int   g_csr[EMAX];
__device__ int   g_bsums[256];
__device__ float g_gb[3 * HD];                       // combined gate biases (i,g,o)
__device__ __align__(16) __nv_bfloat16 g_wb[6 * 2 * HD * HD];  // [plane][hi/lo][128*128]
// planes: 0,1,2 = W_ih gate blocks (i,g,o) as [n][k]; 3 = W1^T; 4 = W2^T; 5 = W3

__device__ __forceinline__ void split_bf16(float v, __nv_bfloat16& h, __nv_bfloat16& l) {
    h = __float2bfloat16(v);
    l = __float2bfloat16(v - __bfloat162float(h));
}

__device__ __forceinline__ uint32_t smem_u32(const void* p) {
    uint32_t a;
    asm("{ .reg .u64 t; cvta.to.shared.u64 t, %1; cvt.u32.u64 %0, t; }" : "=r"(a) : "l"(p));
    return a;
}

#define LDSM4(r, addr) \
    asm volatile("ldmatrix.sync.aligned.m8n8.x4.shared.b16 {%0,%1,%2,%3}, [%4];" \
        : "=r"((r)[0]), "=r"((r)[1]), "=r"((r)[2]), "=r"((r)[3]) : "r"(addr))

// ================= prep =================
__global__ void prep_weights(const float* __restrict__ Wih,
                             const float* __restrict__ W1,
                             const float* __restrict__ W2,
                             const float* __restrict__ W3,
                             const float* __restrict__ bih,
                             const float* __restrict__ bhh) {
    int idx = blockIdx.x * blockDim.x + threadIdx.x;
    if (idx >= HD * HD) return;
    int nn = idx >> 7, kk = idx & 127;
    const int G[3] = {0, 256, 384};
    float src[6];
    src[0] = Wih[(G[0] + nn) * HD + kk];
    src[1] = Wih[(G[1] + nn) * HD + kk];
    src[2] = Wih[(G[2] + nn) * HD + kk];
    src[3] = W1[kk * HD + nn];
    src[4] = W2[kk * HD + nn];
    src[5] = W3[nn * HD + kk];
#pragma unroll
    for (int p = 0; p < 6; p++) {
        __nv_bfloat16 h, l;
        split_bf16(src[p], h, l);
        g_wb[p * 32768 + idx] = h;
        g_wb[p * 32768 + 16384 + idx] = l;
    }
    if (idx < 3 * HD) {
        int p = idx / HD, j = idx % HD;
        g_gb[idx] = bih[G[p] + j] + bhh[G[p] + j];
    }
}

// ================= degree / scan / CSR =================
__global__ void zero_deg(int n) {
    int i = blockIdx.x * blockDim.x + threadIdx.x;
    if (i < n) g_deg[i] = 0;
}
__global__ void deg_count(const int* __restrict__ ei, int e) {
    int i = blockIdx.x * blockDim.x + threadIdx.x;
    if (i < e) atomicAdd(&g_deg[ei[e + i]], 1);
}
__global__ void scan1(int n) {
    __shared__ int sm[1024];
    int t = threadIdx.x, i = blockIdx.x * 1024 + t;
    int v = (i < n) ? g_deg[i] : 0;
    if (i < n) g_dinv[i] = rsqrtf((float)v + 1.0f);
    sm[t] = v; __syncthreads();
    for (int o = 1; o < 1024; o <<= 1) {
        int tmp = (t >= o) ? sm[t - o] : 0; __syncthreads();
        sm[t] += tmp; __syncthreads();
    }
    if (i < n) g_off[i] = sm[t] - v;
    if (t == 1023) g_bsums[blockIdx.x] = sm[1023];
}
__global__ void scan2(int nb) {
    __shared__ int sm[128];
    int t = threadIdx.x;
    int v = (t < nb) ? g_bsums[t] : 0;
    sm[t] = v; __syncthreads();
    for (int o = 1; o < 128; o <<= 1) {
        int tmp = (t >= o) ? sm[t - o] : 0; __syncthreads();
        sm[t] += tmp; __syncthreads();
    }
    if (t < nb) g_bsums[t] = sm[t] - v;
}
__global__ void scan3(int n) {
    int i = blockIdx.x * blockDim.x + threadIdx.x;
    if (i < n) {
        int o = g_off[i] + g_bsums[i >> 10];
        g_off[i] = o; g_cur[i] = o;
    }
}
__global__ void csr_fill(const int* __restrict__ ei, int e) {
    int i = blockIdx.x * blockDim.x + threadIdx.x;
    if (i < e) {
        int d = ei[e + i];
        g_csr[atomicAdd(&g_cur[d], 1)] = ei[i];
    }
}

// ================= mma helper =================
__device__ __forceinline__ void mma_bf16(float* d, const uint32_t* a, const uint32_t* b) {
    asm volatile(
        "mma.sync.aligned.m16n8k16.row.col.f32.bf16.bf16.f32 "
        "{%0,%1,%2,%3}, {%4,%5,%6,%7}, {%8,%9}, {%0,%1,%2,%3};"
        : "+f"(d[0]), "+f"(d[1]), "+f"(d[2]), "+f"(d[3])
        : "r"(a[0]), "r"(a[1]), "r"(a[2]), "r"(a[3]), "r"(b[0]), "r"(b[1]));
}

// ================= fused LSTM =================
#define SMS2 272
#define BSTR 144
#define L_AHI 0
#define L_ALO 17408
#define L_BHI 34816
#define L_BLO 53248
#define L_TOT 71680

__global__ void __launch_bounds__(256, 2)
lstm_fused(const float* __restrict__ z, int n) {
    extern __shared__ char sm[];
    uint32_t sbase = smem_u32(sm);
    int tid = threadIdx.x, lane = tid & 31, wid = tid >> 5;
    int gid = lane >> 2, tig = lane & 3;
    int wm = wid >> 2, wn = wid & 3;            // 2 m x 4 n warps
    int r0 = blockIdx.x * 64;

    // ---- load + split A (64 x 128) ----
    for (int i = tid; i < 64 * 32; i += 256) {
        int row = i >> 5, q = i & 31;
        float4 v = make_float4(0.f, 0.f, 0.f, 0.f);
        if (r0 + row < n) v = *(const float4*)(z + (size_t)(r0 + row) * HD + q * 4);
        __nv_bfloat16 h[4], l[4];
        split_bf16(v.x, h[0], l[0]); split_bf16(v.y, h[1], l[1]);
        split_bf16(v.z, h[2], l[2]); split_bf16(v.w, h[3], l[3]);
        *(uint2*)(sm + L_AHI + row * SMS2 + q * 8) = *(const uint2*)h;
        *(uint2*)(sm + L_ALO + row * SMS2 + q * 8) = *(const uint2*)l;
    }

    // ldmatrix per-lane address components
    uint32_t aAl = (uint32_t)((wm * 32 + (lane & 15)) * SMS2 + ((lane >> 4) << 3) * 2);
    uint32_t aBl = (uint32_t)((wn * 32 + ((lane >> 4) << 3) + (lane & 7)) * BSTR
                              + ((lane >> 3) & 1) * 16);

    float cp[2][4][4];
    float acc[2][4][4];

#pragma unroll 1
    for (int p = 0; p < 3; p++) {
#pragma unroll
        for (int mt = 0; mt < 2; mt++)
#pragma unroll
            for (int nt = 0; nt < 4; nt++)
#pragma unroll
                for (int q = 0; q < 4; q++) acc[mt][nt][q] = 0.0f;

#pragma unroll 1
        for (int kc = 0; kc < 2; kc++) {
            __syncthreads();
            for (int i = tid; i < 128 * 8; i += 256) {
                int row = i >> 3, q = i & 7;
                uint4 h = *(const uint4*)(g_wb + (size_t)p * 32768 + row * HD + kc * 64 + q * 8);
                uint4 l = *(const uint4*)(g_wb + (size_t)p * 32768 + 16384 + row * HD + kc * 64 + q * 8);
                *(uint4*)(sm + L_BHI + row * BSTR + q * 16) = h;
                *(uint4*)(sm + L_BLO + row * BSTR + q * 16) = l;
            }
            __syncthreads();

#pragma unroll
            for (int s = 0; s < 3; s++) {
                uint32_t Ab = sbase + ((s == 1) ? L_ALO : L_AHI) + aAl + kc * 128;
                uint32_t Bb = sbase + ((s == 2) ? L_BLO : L_BHI) + aBl;
#pragma unroll
                for (int ks = 0; ks < 4; ks++) {
                    uint32_t ra0[4], ra1[4], rb0[4], rb1[4];
                    LDSM4(ra0, Ab + ks * 32);
                    LDSM4(ra1, Ab + 16 * SMS2 + ks * 32);
                    LDSM4(rb0, Bb + ks * 32);
                    LDSM4(rb1, Bb + 16 * BSTR + ks * 32);
                    mma_bf16(acc[0][0], ra0, rb0 + 0);
                    mma_bf16(acc[0][1], ra0, rb0 + 2);
                    mma_bf16(acc[0][2], ra0, rb1 + 0);
                    mma_bf16(acc[0][3], ra0, rb1 + 2);
                    mma_bf16(acc[1][0], ra1, rb0 + 0);
                    mma_bf16(acc[1][1], ra1, rb0 + 2);
                    mma_bf16(acc[1][2], ra1, rb1 + 0);
                    mma_bf16(acc[1][3], ra1, rb1 + 2);
                }
            }
        }

        // ---- plane epilogue (registers only) ----
#pragma unroll
        for (int mt = 0; mt < 2; mt++) {
#pragma unroll
            for (int nt = 0; nt < 4; nt++) {
                int col = wn * 32 + nt * 8 + tig * 2;
                float2 bg = *(const float2*)(g_gb + p * HD + col);
#pragma unroll
                for (int q = 0; q < 4; q++) {
                    float gv = acc[mt][nt][q] + ((q & 1) ? bg.y : bg.x);
                    if (p == 0)      cp[mt][nt][q] = 1.0f / (1.0f + __expf(-gv));
                    else if (p == 1) cp[mt][nt][q] = cp[mt][nt][q] * tanhf(gv);
                    else             cp[mt][nt][q] = (1.0f / (1.0f + __expf(-gv))) * tanhf(cp[mt][nt][q]);
                }
            }
        }
    }

    // ---- store h ----
#pragma unroll
    for (int mt = 0; mt < 2; mt++) {
        int row0 = r0 + wm * 32 + mt * 16 + gid;
        int row1 = row0 + 8;
#pragma unroll
        for (int nt = 0; nt < 4; nt++) {
            int col = wn * 32 + nt * 8 + tig * 2;
            if (row0 < n) *(float2*)(g_h + (size_t)row0 * HD + col) = make_float2(cp[mt][nt][0], cp[mt][nt][1]);
            if (row1 < n) *(float2*)(g_h + (size_t)row1 * HD + col) = make_float2(cp[mt][nt][2], cp[mt][nt][3]);
        }
    }
}

// ================= mma.sync split GEMM (single plane) =================
#define SMS 144
template <int MODE, bool ARELU>
__global__ void __launch_bounds__(256, 2)
mma_gemm(const float* __restrict__ A, const __nv_bfloat16* __restrict__ Bp,
         const float* __restrict__ bias, const float* __restrict__ dinv,
         float* __restrict__ C, int n) {
    extern __shared__ char sm[];
    const int AHI = 0, ALO = 18432, BHI = 36864, BLO = 55296;
    uint32_t sbase = smem_u32(sm);

    int tid = threadIdx.x, lane = tid & 31, wid = tid >> 5;
    int gid = lane >> 2, tig = lane & 3;
    int wm = wid & 3, wn = wid >> 2;
    int r0 = blockIdx.x * 128;

    uint32_t aAl = (uint32_t)((wm * 32 + (lane & 15)) * SMS + ((lane >> 4) << 3) * 2);
    uint32_t aBl = (uint32_t)((wn * 64 + ((lane >> 4) << 3) + (lane & 7)) * SMS
                              + ((lane >> 3) & 1) * 16);

    float acc[2][8][4];
#pragma unroll
    for (int mt = 0; mt < 2; mt++)
#pragma unroll
        for (int nt = 0; nt < 8; nt++)
#pragma unroll
            for (int q = 0; q < 4; q++) acc[mt][nt][q] = 0.0f;

#pragma unroll 1
    for (int kc = 0; kc < 2; kc++) {
        for (int i = tid; i < 128 * 16; i += 256) {
            int row = i >> 4, q = i & 15;
            float4 v = make_float4(0.f, 0.f, 0.f, 0.f);
            if (r0 + row < n)
                v = *(const float4*)(A + (size_t)(r0 + row) * HD + kc * 64 + q * 4);
            if (ARELU) {
                v.x = fmaxf(v.x, 0.f); v.y = fmaxf(v.y, 0.f);
                v.z = fmaxf(v.z, 0.f); v.w = fmaxf(v.w, 0.f);
            }
            __nv_bfloat16 h[4], l[4];
            split_bf16(v.x, h[0], l[0]); split_bf16(v.y, h[1], l[1]);
            split_bf16(v.z, h[2], l[2]); split_bf16(v.w, h[3], l[3]);
            *(uint2*)(sm + AHI + row * SMS + q * 8) = *(const uint2*)h;
            *(uint2*)(sm + ALO + row * SMS + q * 8) = *(const uint2*)l;
        }
        for (int i = tid; i < 128 * 8; i += 256) {
            int row = i >> 3, q = i & 7;
            uint4 h = *(const uint4*)(Bp + (size_t)row * HD + kc * 64 + q * 8);
            uint4 l = *(const uint4*)(Bp + 16384 + (size_t)row * HD + kc * 64 + q * 8);
            *(uint4*)(sm + BHI + row * SMS + q * 16) = h;
            *(uint4*)(sm + BLO + row * SMS + q * 16) = l;
        }
        __syncthreads();

#pragma unroll
        for (int s = 0; s < 3; s++) {
            uint32_t Ab = sbase + ((s == 1) ? ALO : AHI) + aAl;
            uint32_t Bb = sbase + ((s == 2) ? BLO : BHI) + aBl;
#pragma unroll
            for (int ks = 0; ks < 4; ks++) {
                uint32_t ra0[4], ra1[4];
                LDSM4(ra0, Ab + ks * 32);
                LDSM4(ra1, Ab + 16 * SMS + ks * 32);
#pragma unroll
                for (int nt2 = 0; nt2 < 4; nt2++) {
                    uint32_t rb[4];
                    LDSM4(rb, Bb + nt2 * 16 * SMS + ks * 32);
                    mma_bf16(acc[0][nt2 * 2 + 0], ra0, rb + 0);
                    mma_bf16(acc[0][nt2 * 2 + 1], ra0, rb + 2);
                    mma_bf16(acc[1][nt2 * 2 + 0], ra1, rb + 0);
                    mma_bf16(acc[1][nt2 * 2 + 1], ra1, rb + 2);
                }
            }
        }
        __syncthreads();
    }

#pragma unroll
    for (int mt = 0; mt < 2; mt++) {
        int row0 = r0 + wm * 32 + mt * 16 + gid;
        int row1 = row0 + 8;
        float dv0 = 0.f, dv1 = 0.f;
        if (MODE == 1) {
            dv0 = (row0 < n) ? dinv[row0] : 0.f;
            dv1 = (row1 < n) ? dinv[row1] : 0.f;
        }
#pragma unroll
        for (int nt = 0; nt < 8; nt++) {
            int col = wn * 64 + nt * 8 + tig * 2;
            float d0 = acc[mt][nt][0], d1 = acc[mt][nt][1];
            float d2 = acc[mt][nt][2], d3 = acc[mt][nt][3];
            if (MODE == 1) { d0 *= dv0; d1 *= dv0; d2 *= dv1; d3 *= dv1; }
            if (MODE == 2) {
                float b0 = __ldg(bias + col), b1 = __ldg(bias + col + 1);
                d0 = fmaxf(d0 + b0, 0.f); d1 = fmaxf(d1 + b1, 0.f);
                d2 = fmaxf(d2 + b0, 0.f); d3 = fmaxf(d3 + b1, 0.f);
            }
            if (row0 < n) *(float2*)(C + (size_t)row0 * HD + col) = make_float2(d0, d1);
            if (row1 < n) *(float2*)(C + (size_t)row1 * HD + col) = make_float2(d2, d3);
        }
    }
}

// ================= CSR aggregation =================
__global__ void aggregate_k(const float* __restrict__ t2,
                            const float* __restrict__ bias,
                            float* __restrict__ out, int n) {
    int w = (blockIdx.x * blockDim.x + threadIdx.x) >> 5;
    int lane = threadIdx.x & 31;
    if (w >= n) return;
    const float4* T = (const float4*)t2;
    float4 acc = T[(size_t)w * 32 + lane];
    int s0 = g_off[w], cnt = g_deg[w];
    int i = 0;
    for (; i + 7 < cnt; i += 8) {
        int ix[8];
#pragma unroll
        for (int u = 0; u < 8; u++) ix[u] = g_csr[s0 + i + u];
        float4 v[8];
#pragma unroll
        for (int u = 0; u < 8; u++) v[u] = T[(size_t)ix[u] * 32 + lane];
#pragma unroll
        for (int u = 0; u < 8; u++) {
            acc.x += v[u].x; acc.y += v[u].y; acc.z += v[u].z; acc.w += v[u].w;
        }
    }
    for (; i < cnt; i++) {
        float4 v = T[(size_t)g_csr[s0 + i] * 32 + lane];
        acc.x += v.x; acc.y += v.y; acc.z += v.z; acc.w += v.w;
    }
    float dvv = g_dinv[w];
    float4 b4 = ((const float4*)bias)[lane];
    float4 o;
    o.x = acc.x * dvv + b4.x; o.y = acc.y * dvv + b4.y;
    o.z = acc.z * dvv + b4.z; o.w = acc.w * dvv + b4.w;
    ((float4*)out)[(size_t)w * 32 + lane] = o;
}

// ================= launch =================
#define SMEM_GEMM 73728

extern "C" void kernel_launch(void* const* d_in, const int* in_sizes, int n_in,
                              void* d_out, int out_size) {
    const float* z   = (const float*)d_in[0];
    const int*   ei  = (const int*)d_in[1];
    const float* Wih = (const float*)d_in[2];
    const float* bih = (const float*)d_in[4];
    const float* bhh = (const float*)d_in[5];
    const float* W1  = (const float*)d_in[6];
    const float* b1  = (const float*)d_in[7];
    const float* W2  = (const float*)d_in[8];
    const float* b2  = (const float*)d_in[9];
    const float* W3  = (const float*)d_in[10];
    const float* b3  = (const float*)d_in[11];

    int n = in_sizes[0] / HD;
    int e = in_sizes[1] / 2;
    float* out = (float*)d_out;

    float *p_h, *p_t, *p_s, *p_dinv;
    __nv_bfloat16* p_wb;
    cudaGetSymbolAddress((void**)&p_h, g_h);
    cudaGetSymbolAddress((void**)&p_t, g_t);
    cudaGetSymbolAddress((void**)&p_s, g_s);
    cudaGetSymbolAddress((void**)&p_dinv, g_dinv);
    cudaGetSymbolAddress((void**)&p_wb, g_wb);

    cudaFuncSetAttribute(lstm_fused, cudaFuncAttributeMaxDynamicSharedMemorySize, L_TOT);
    cudaFuncSetAttribute(mma_gemm<1, false>, cudaFuncAttributeMaxDynamicSharedMemorySize, SMEM_GEMM);
    cudaFuncSetAttribute(mma_gemm<1, true>,  cudaFuncAttributeMaxDynamicSharedMemorySize, SMEM_GEMM);
    cudaFuncSetAttribute(mma_gemm<2, false>, cudaFuncAttributeMaxDynamicSharedMemorySize, SMEM_GEMM);

    int nb = (n + 1023) / 1024;
    // same ordering: ncu capture slot lands on lstm_fused
    prep_weights<<<(HD * HD + 255) / 256, 256>>>(Wih, W1, W2, W3, bih, bhh);   // 1
    zero_deg<<<(n + 255) / 256, 256>>>(n);                                     // 2
    deg_count<<<(e + 255) / 256, 256>>>(ei, e);                                // 3
    lstm_fused<<<(n + 63) / 64, 256, L_TOT>>>(z, n);                           // 4 <- profiled
    scan1<<<nb, 1024>>>(n);
    scan2<<<1, 128>>>(nb);
    scan3<<<(n + 255) / 256, 256>>>(n);
    csr_fill<<<(e + 255) / 256, 256>>>(ei, e);

    dim3 gg((n + 127) / 128);
    mma_gemm<1, false><<<gg, 256, SMEM_GEMM>>>(p_h, p_wb + 3 * 32768, nullptr, p_dinv, p_t, n);
    aggregate_k<<<((size_t)n * 32 + 255) / 256, 256>>>(p_t, b1, p_s, n);
    mma_gemm<1, true><<<gg, 256, SMEM_GEMM>>>(p_s, p_wb + 4 * 32768, nullptr, p_dinv, p_t, n);
    aggregate_k<<<((size_t)n * 32 + 255) / 256, 256>>>(p_t, b2, p_s, n);
    mma_gemm<2, false><<<gg, 256, SMEM_GEMM>>>(p_s, p_wb + 5 * 32768, b3, nullptr, out, n);
}

// round 11
// speedup vs baseline: 1.3407x; 1.3407x over previous
#include <cuda_runtime.h>
#include <cuda_fp16.h>
#include <math.h>
#include <stdint.h>

#define HD 128
#define NMAX 100000
#define EMAX 1600000

// ================= scratch =================
__device__ __align__(16) __half g_hf[(size_t)NMAX * HD];
__device__ __align__(16) __half g_tf[(size_t)NMAX * HD];
__device__ __align__(16) __half g_sf[(size_t)NMAX * HD];
__device__ float g_dinv[NMAX];
__device__ int   g_deg[NMAX];
__device__ int   g_off[NMAX];
__device__ int   g_cur[NMAX];
__device__ int   g_csr[EMAX];
__device__ int   g_bsums[256];
__device__ float g_gb[3 * HD];                                  // gate biases (i,g,o)
__device__ __align__(16) __half g_wf[6 * 2 * HD * HD];          // [plane][hi/lo][128*128] fp16
// planes: 0,1,2 = W_ih gate blocks (i,g,o) [n][k]; 3 = W1^T; 4 = W2^T; 5 = W3

__device__ __forceinline__ uint32_t smem_u32(const void* p) {
    uint32_t a;
    asm("{ .reg .u64 t; cvta.to.shared.u64 t, %1; cvt.u32.u64 %0, t; }" : "=r"(a) : "l"(p));
    return a;
}
#define LDSM4(r, addr) \
    asm volatile("ldmatrix.sync.aligned.m8n8.x4.shared.b16 {%0,%1,%2,%3}, [%4];" \
        : "=r"((r)[0]), "=r"((r)[1]), "=r"((r)[2]), "=r"((r)[3]) : "r"(addr))

__device__ __forceinline__ void mma_f16(float* d, const uint32_t* a, const uint32_t* b) {
    asm volatile(
        "mma.sync.aligned.m16n8k16.row.col.f32.f16.f16.f32 "
        "{%0,%1,%2,%3}, {%4,%5,%6,%7}, {%8,%9}, {%0,%1,%2,%3};"
        : "+f"(d[0]), "+f"(d[1]), "+f"(d[2]), "+f"(d[3])
        : "r"(a[0]), "r"(a[1]), "r"(a[2]), "r"(a[3]), "r"(b[0]), "r"(b[1]));
}

// ================= prep: split weights to fp16 hi/lo =================
__global__ void prep_weights(const float* __restrict__ Wih,
                             const float* __restrict__ W1,
                             const float* __restrict__ W2,
                             const float* __restrict__ W3,
                             const float* __restrict__ bih,
                             const float* __restrict__ bhh) {
    int idx = blockIdx.x * blockDim.x + threadIdx.x;
    if (idx >= HD * HD) return;
    int nn = idx >> 7, kk = idx & 127;
    const int G[3] = {0, 256, 384};
    float src[6];
    src[0] = Wih[(G[0] + nn) * HD + kk];
    src[1] = Wih[(G[1] + nn) * HD + kk];
    src[2] = Wih[(G[2] + nn) * HD + kk];
    src[3] = W1[kk * HD + nn];
    src[4] = W2[kk * HD + nn];
    src[5] = W3[nn * HD + kk];
#pragma unroll
    for (int p = 0; p < 6; p++) {
        __half h = __float2half_rn(src[p]);
        __half l = __float2half_rn(src[p] - __half2float(h));
        g_wf[p * 32768 + idx] = h;
        g_wf[p * 32768 + 16384 + idx] = l;
    }
    if (idx < 3 * HD) {
        int p = idx / HD, j = idx % HD;
        g_gb[idx] = bih[G[p] + j] + bhh[G[p] + j];
    }
}

// ================= degree / scan / CSR =================
__global__ void zero_deg(int n) {
    int i = blockIdx.x * blockDim.x + threadIdx.x;
    if (i < n) g_deg[i] = 0;
}
__global__ void deg_count(const int* __restrict__ ei, int e) {
    int i = blockIdx.x * blockDim.x + threadIdx.x;
    if (i < e) atomicAdd(&g_deg[ei[e + i]], 1);
}
__global__ void scan1(int n) {
    __shared__ int sm[1024];
    int t = threadIdx.x, i = blockIdx.x * 1024 + t;
    int v = (i < n) ? g_deg[i] : 0;
    if (i < n) g_dinv[i] = rsqrtf((float)v + 1.0f);
    sm[t] = v; __syncthreads();
    for (int o = 1; o < 1024; o <<= 1) {
        int tmp = (t >= o) ? sm[t - o] : 0; __syncthreads();
        sm[t] += tmp; __syncthreads();
    }
    if (i < n) g_off[i] = sm[t] - v;
    if (t == 1023) g_bsums[blockIdx.x] = sm[1023];
}
__global__ void scan2(int nb) {
    __shared__ int sm[128];
    int t = threadIdx.x;
    int v = (t < nb) ? g_bsums[t] : 0;
    sm[t] = v; __syncthreads();
    for (int o = 1; o < 128; o <<= 1) {
        int tmp = (t >= o) ? sm[t - o] : 0; __syncthreads();
        sm[t] += tmp; __syncthreads();
    }
    if (t < nb) g_bsums[t] = sm[t] - v;
}
__global__ void scan3(int n) {
    int i = blockIdx.x * blockDim.x + threadIdx.x;
    if (i < n) {
        int o = g_off[i] + g_bsums[i >> 10];
        g_off[i] = o; g_cur[i] = o;
    }
}
__global__ void csr_fill(const int* __restrict__ ei, int e) {
    int i = blockIdx.x * blockDim.x + threadIdx.x;
    if (i < e) {
        int d = ei[e + i];
        g_csr[atomicAdd(&g_cur[d], 1)] = ei[i];
    }
}

// ================= fused LSTM: h = act(z @ {Wi,Wg,Wo}^T + gb), fp16 x2 =================
#define ASTR 272          // A row stride bytes (full K=128 fp16 + pad)
#define BSTR 144          // B chunk row stride bytes (64 fp16 + pad)
#define L_A   0
#define L_BHI 17408
#define L_BLO 35840
#define L_TOT 54272

__global__ void __launch_bounds__(256, 2)
lstm_fused(const float* __restrict__ z, int n) {
    extern __shared__ char sm[];
    uint32_t sbase = smem_u32(sm);
    int tid = threadIdx.x, lane = tid & 31, wid = tid >> 5;
    int gid = lane >> 2, tig = lane & 3;
    int wm = wid >> 2, wn = wid & 3;            // 2 m x 4 n warps
    int r0 = blockIdx.x * 64;

    // ---- load z (fp32) -> fp16 A (64 x 128), once ----
    for (int i = tid; i < 64 * 16; i += 256) {
        int row = i >> 4, q = i & 15;           // q*8 cols
        float4 v1 = make_float4(0.f, 0.f, 0.f, 0.f), v2 = v1;
        if (r0 + row < n) {
            v1 = *(const float4*)(z + (size_t)(r0 + row) * HD + q * 8);
            v2 = *(const float4*)(z + (size_t)(r0 + row) * HD + q * 8 + 4);
        }
        __half2 h0 = __float22half2_rn(make_float2(v1.x, v1.y));
        __half2 h1 = __float22half2_rn(make_float2(v1.z, v1.w));
        __half2 h2 = __float22half2_rn(make_float2(v2.x, v2.y));
        __half2 h3 = __float22half2_rn(make_float2(v2.z, v2.w));
        uint4 u = make_uint4(*(uint32_t*)&h0, *(uint32_t*)&h1, *(uint32_t*)&h2, *(uint32_t*)&h3);
        *(uint4*)(sm + L_A + row * ASTR + q * 16) = u;
    }

    uint32_t aAl = (uint32_t)((wm * 32 + (lane & 15)) * ASTR + ((lane >> 4) << 3) * 2);
    uint32_t aBl = (uint32_t)((wn * 32 + ((lane >> 4) << 3) + (lane & 7)) * BSTR
                              + ((lane >> 3) & 1) * 16);

    float cp[2][4][4];
    float acc[2][4][4];

#pragma unroll 1
    for (int p = 0; p < 3; p++) {
#pragma unroll
        for (int mt = 0; mt < 2; mt++)
#pragma unroll
            for (int nt = 0; nt < 4; nt++)
#pragma unroll
                for (int q = 0; q < 4; q++) acc[mt][nt][q] = 0.0f;

#pragma unroll 1
        for (int kc = 0; kc < 2; kc++) {
            __syncthreads();
            // load B plane p, k-chunk kc: hi + lo (128 n x 64 k fp16)
            for (int i = tid; i < 128 * 8; i += 256) {
                int row = i >> 3, q = i & 7;
                uint4 h = __ldg((const uint4*)(g_wf + (size_t)p * 32768 + row * HD + kc * 64 + q * 8));
                uint4 l = __ldg((const uint4*)(g_wf + (size_t)p * 32768 + 16384 + row * HD + kc * 64 + q * 8));
                *(uint4*)(sm + L_BHI + row * BSTR + q * 16) = h;
                *(uint4*)(sm + L_BLO + row * BSTR + q * 16) = l;
            }
            __syncthreads();

            uint32_t Ab = sbase + L_A + aAl + kc * 128;
#pragma unroll
            for (int ks = 0; ks < 4; ks++) {
                uint32_t ra0[4], ra1[4];
                LDSM4(ra0, Ab + ks * 32);
                LDSM4(ra1, Ab + 16 * ASTR + ks * 32);
#pragma unroll
                for (int s = 0; s < 2; s++) {
                    uint32_t Bb = sbase + ((s == 1) ? L_BLO : L_BHI) + aBl + ks * 32;
                    uint32_t rb0[4], rb1[4];
                    LDSM4(rb0, Bb);
                    LDSM4(rb1, Bb + 16 * BSTR);
                    mma_f16(acc[0][0], ra0, rb0 + 0);
                    mma_f16(acc[0][1], ra0, rb0 + 2);
                    mma_f16(acc[0][2], ra0, rb1 + 0);
                    mma_f16(acc[0][3], ra0, rb1 + 2);
                    mma_f16(acc[1][0], ra1, rb0 + 0);
                    mma_f16(acc[1][1], ra1, rb0 + 2);
                    mma_f16(acc[1][2], ra1, rb1 + 0);
                    mma_f16(acc[1][3], ra1, rb1 + 2);
                }
            }
        }

        // ---- plane epilogue (registers only) ----
#pragma unroll
        for (int mt = 0; mt < 2; mt++) {
#pragma unroll
            for (int nt = 0; nt < 4; nt++) {
                int col = wn * 32 + nt * 8 + tig * 2;
                float2 bg = *(const float2*)(g_gb + p * HD + col);
#pragma unroll
                for (int q = 0; q < 4; q++) {
                    float gv = acc[mt][nt][q] + ((q & 1) ? bg.y : bg.x);
                    if (p == 0)      cp[mt][nt][q] = 1.0f / (1.0f + __expf(-gv));
                    else if (p == 1) cp[mt][nt][q] = cp[mt][nt][q] * tanhf(gv);
                    else             cp[mt][nt][q] = (1.0f / (1.0f + __expf(-gv))) * tanhf(cp[mt][nt][q]);
                }
            }
        }
    }

    // ---- store h as fp16 ----
#pragma unroll
    for (int mt = 0; mt < 2; mt++) {
        int row0 = r0 + wm * 32 + mt * 16 + gid;
        int row1 = row0 + 8;
#pragma unroll
        for (int nt = 0; nt < 4; nt++) {
            int col = wn * 32 + nt * 8 + tig * 2;
            __half2 v0 = __float22half2_rn(make_float2(cp[mt][nt][0], cp[mt][nt][1]));
            __half2 v1 = __float22half2_rn(make_float2(cp[mt][nt][2], cp[mt][nt][3]));
            if (row0 < n) *(uint32_t*)(g_hf + (size_t)row0 * HD + col) = *(uint32_t*)&v0;
            if (row1 < n) *(uint32_t*)(g_hf + (size_t)row1 * HD + col) = *(uint32_t*)&v1;
        }
    }
}

// ================= mma GEMM: C = epi(A16 @ B), fp16 x2 (B hi/lo) =================
// MODE 1: t = acc * dinv[row] -> fp16 C16
// MODE 2: out = relu(acc + bias[col]) -> fp32 C32
#define SMS 144
#define G_A   0
#define G_BHI 18432
#define G_BLO 36864
#define SMEM_GEMM 55296

template <int MODE, bool ARELU>
__global__ void __launch_bounds__(256, 2)
mma_gemm(const __half* __restrict__ A, const __half* __restrict__ Bp,
         const float* __restrict__ bias, const float* __restrict__ dinv,
         __half* __restrict__ C16, float* __restrict__ C32, int n) {
    extern __shared__ char sm[];
    uint32_t sbase = smem_u32(sm);

    int tid = threadIdx.x, lane = tid & 31, wid = tid >> 5;
    int gid = lane >> 2, tig = lane & 3;
    int wm = wid & 3, wn = wid >> 2;
    int r0 = blockIdx.x * 128;

    uint32_t aAl = (uint32_t)((wm * 32 + (lane & 15)) * SMS + ((lane >> 4) << 3) * 2);
    uint32_t aBl = (uint32_t)((wn * 64 + ((lane >> 4) << 3) + (lane & 7)) * SMS
                              + ((lane >> 3) & 1) * 16);

    float acc[2][8][4];
#pragma unroll
    for (int mt = 0; mt < 2; mt++)
#pragma unroll
        for (int nt = 0; nt < 8; nt++)
#pragma unroll
            for (int q = 0; q < 4; q++) acc[mt][nt][q] = 0.0f;

    const __half2 z2 = __float2half2_rn(0.0f);

#pragma unroll 1
    for (int kc = 0; kc < 2; kc++) {
        // A chunk: 128 rows x 64 k, fp16 direct
        for (int i = tid; i < 128 * 8; i += 256) {
            int row = i >> 3, q = i & 7;
            uint4 u = make_uint4(0u, 0u, 0u, 0u);
            if (r0 + row < n)
                u = *(const uint4*)(A + (size_t)(r0 + row) * HD + kc * 64 + q * 8);
            if (ARELU) {
                __half2* hp = (__half2*)&u;
#pragma unroll
                for (int j = 0; j < 4; j++) hp[j] = __hmax2(hp[j], z2);
            }
            *(uint4*)(sm + G_A + row * SMS + q * 16) = u;
        }
        // B chunk hi/lo
        for (int i = tid; i < 128 * 8; i += 256) {
            int row = i >> 3, q = i & 7;
            uint4 h = __ldg((const uint4*)(Bp + (size_t)row * HD + kc * 64 + q * 8));
            uint4 l = __ldg((const uint4*)(Bp + 16384 + (size_t)row * HD + kc * 64 + q * 8));
            *(uint4*)(sm + G_BHI + row * SMS + q * 16) = h;
            *(uint4*)(sm + G_BLO + row * SMS + q * 16) = l;
        }
        __syncthreads();

#pragma unroll
        for (int ks = 0; ks < 4; ks++) {
            uint32_t ra0[4], ra1[4];
            LDSM4(ra0, sbase + G_A + aAl + ks * 32);
            LDSM4(ra1, sbase + G_A + aAl + 16 * SMS + ks * 32);
#pragma unroll
            for (int s = 0; s < 2; s++) {
                uint32_t Bb = sbase + ((s == 1) ? G_BLO : G_BHI) + aBl + ks * 32;
#pragma unroll
                for (int nt2 = 0; nt2 < 4; nt2++) {
                    uint32_t rb[4];
                    LDSM4(rb, Bb + nt2 * 16 * SMS);
                    mma_f16(acc[0][nt2 * 2 + 0], ra0, rb + 0);
                    mma_f16(acc[0][nt2 * 2 + 1], ra0, rb + 2);
                    mma_f16(acc[1][nt2 * 2 + 0], ra1, rb + 0);
                    mma_f16(acc[1][nt2 * 2 + 1], ra1, rb + 2);
                }
            }
        }
        __syncthreads();
    }

#pragma unroll
    for (int mt = 0; mt < 2; mt++) {
        int row0 = r0 + wm * 32 + mt * 16 + gid;
        int row1 = row0 + 8;
        float dv0 = 0.f, dv1 = 0.f;
        if (MODE == 1) {
            dv0 = (row0 < n) ? dinv[row0] : 0.f;
            dv1 = (row1 < n) ? dinv[row1] : 0.f;
        }
#pragma unroll
        for (int nt = 0; nt < 8; nt++) {
            int col = wn * 64 + nt * 8 + tig * 2;
            float d0 = acc[mt][nt][0], d1 = acc[mt][nt][1];
            float d2 = acc[mt][nt][2], d3 = acc[mt][nt][3];
            if (MODE == 1) {
                __half2 v0 = __float22half2_rn(make_float2(d0 * dv0, d1 * dv0));
                __half2 v1 = __float22half2_rn(make_float2(d2 * dv1, d3 * dv1));
                if (row0 < n) *(uint32_t*)(C16 + (size_t)row0 * HD + col) = *(uint32_t*)&v0;
                if (row1 < n) *(uint32_t*)(C16 + (size_t)row1 * HD + col) = *(uint32_t*)&v1;
            } else {
                float b0 = __ldg(bias + col), b1 = __ldg(bias + col + 1);
                if (row0 < n) *(float2*)(C32 + (size_t)row0 * HD + col) =
                    make_float2(fmaxf(d0 + b0, 0.f), fmaxf(d1 + b1, 0.f));
                if (row1 < n) *(float2*)(C32 + (size_t)row1 * HD + col) =
                    make_float2(fmaxf(d2 + b0, 0.f), fmaxf(d3 + b1, 0.f));
            }
        }
    }
}

// ================= CSR aggregation, fp16 in/out, fp32 accum =================
__global__ void aggregate_k(const __half* __restrict__ t2,
                            const float* __restrict__ bias,
                            __half* __restrict__ out, int n) {
    int w = (blockIdx.x * blockDim.x + threadIdx.x) >> 5;
    int lane = threadIdx.x & 31;
    if (w >= n) return;
    const uint2* T = (const uint2*)t2;          // 4 halves per lane
    uint2 self = T[(size_t)w * 32 + lane];
    float2 a0 = __half22float2(*(__half2*)&self.x);
    float2 a1 = __half22float2(*(__half2*)&self.y);
    float4 acc = make_float4(a0.x, a0.y, a1.x, a1.y);
    const int* idx = g_csr + g_off[w];
    int cnt = g_deg[w];
    int i = 0;
    for (; i + 7 < cnt; i += 8) {
        int ix[8];
#pragma unroll
        for (int u = 0; u < 8; u++) ix[u] = idx[i + u];
        uint2 v[8];
#pragma unroll
        for (int u = 0; u < 8; u++) v[u] = T[(size_t)ix[u] * 32 + lane];
#pragma unroll
        for (int u = 0; u < 8; u++) {
            float2 f0 = __half22float2(*(__half2*)&v[u].x);
            float2 f1 = __half22float2(*(__half2*)&v[u].y);
            acc.x += f0.x; acc.y += f0.y; acc.z += f1.x; acc.w += f1.y;
        }
    }
    for (; i < cnt; i++) {
        uint2 v = T[(size_t)idx[i] * 32 + lane];
        float2 f0 = __half22float2(*(__half2*)&v.x);
        float2 f1 = __half22float2(*(__half2*)&v.y);
        acc.x += f0.x; acc.y += f0.y; acc.z += f1.x; acc.w += f1.y;
    }
    float dvv = g_dinv[w];
    float4 b4 = ((const float4*)bias)[lane];
    __half2 o0 = __float22half2_rn(make_float2(acc.x * dvv + b4.x, acc.y * dvv + b4.y));
    __half2 o1 = __float22half2_rn(make_float2(acc.z * dvv + b4.z, acc.w * dvv + b4.w));
    uint2 o = make_uint2(*(uint32_t*)&o0, *(uint32_t*)&o1);
    ((uint2*)out)[(size_t)w * 32 + lane] = o;
}

// ================= launch =================
extern "C" void kernel_launch(void* const* d_in, const int* in_sizes, int n_in,
                              void* d_out, int out_size) {
    const float* z   = (const float*)d_in[0];
    const int*   ei  = (const int*)d_in[1];
    const float* Wih = (const float*)d_in[2];
    const float* bih = (const float*)d_in[4];
    const float* bhh = (const float*)d_in[5];
    const float* W1  = (const float*)d_in[6];
    const float* b1  = (const float*)d_in[7];
    const float* W2  = (const float*)d_in[8];
    const float* b2  = (const float*)d_in[9];
    const float* W3  = (const float*)d_in[10];
    const float* b3  = (const float*)d_in[11];

    int n = in_sizes[0] / HD;
    int e = in_sizes[1] / 2;
    float* out = (float*)d_out;

    __half *p_hf, *p_tf, *p_sf, *p_wf;
    float *p_dinv;
    cudaGetSymbolAddress((void**)&p_hf, g_hf);
    cudaGetSymbolAddress((void**)&p_tf, g_tf);
    cudaGetSymbolAddress((void**)&p_sf, g_sf);
    cudaGetSymbolAddress((void**)&p_wf, g_wf);
    cudaGetSymbolAddress((void**)&p_dinv, g_dinv);

    cudaFuncSetAttribute(lstm_fused, cudaFuncAttributeMaxDynamicSharedMemorySize, L_TOT);
    cudaFuncSetAttribute(mma_gemm<1, false>, cudaFuncAttributeMaxDynamicSharedMemorySize, SMEM_GEMM);
    cudaFuncSetAttribute(mma_gemm<1, true>,  cudaFuncAttributeMaxDynamicSharedMemorySize, SMEM_GEMM);
    cudaFuncSetAttribute(mma_gemm<2, false>, cudaFuncAttributeMaxDynamicSharedMemorySize, SMEM_GEMM);

    int nb = (n + 1023) / 1024;
    // ordering: ncu capture slot (4th launch) = lstm_fused
    prep_weights<<<(HD * HD + 255) / 256, 256>>>(Wih, W1, W2, W3, bih, bhh);   // 1
    zero_deg<<<(n + 255) / 256, 256>>>(n);                                     // 2
    deg_count<<<(e + 255) / 256, 256>>>(ei, e);                                // 3
    lstm_fused<<<(n + 63) / 64, 256, L_TOT>>>(z, n);                           // 4 <- profiled
    scan1<<<nb, 1024>>>(n);
    scan2<<<1, 128>>>(nb);
    scan3<<<(n + 255) / 256, 256>>>(n);
    csr_fill<<<(e + 255) / 256, 256>>>(ei, e);

    dim3 gg((n + 127) / 128);
    // conv1 transform: t = (h @ W1) * dinv[row]   (fp16 out)
    mma_gemm<1, false><<<gg, 256, SMEM_GEMM>>>(p_hf, p_wf + 3 * 32768, nullptr, p_dinv, p_tf, nullptr, n);
    aggregate_k<<<((size_t)n * 32 + 255) / 256, 256>>>(p_tf, b1, p_sf, n);
    // conv2 transform: t = (relu(s) @ W2) * dinv[row]
    mma_gemm<1, true><<<gg, 256, SMEM_GEMM>>>(p_sf, p_wf + 4 * 32768, nullptr, p_dinv, p_tf, nullptr, n);
    aggregate_k<<<((size_t)n * 32 + 255) / 256, 256>>>(p_tf, b2, p_sf, n);
    // final: out = relu(s @ W3^T + b3)  (fp32 out)
    mma_gemm<2, false><<<gg, 256, SMEM_GEMM>>>(p_sf, p_wf + 5 * 32768, b3, nullptr, nullptr, out, n);
}

// round 12
// speedup vs baseline: 1.7232x; 1.2853x over previous
#include <cuda_runtime.h>
#include <cuda_fp16.h>
#include <math.h>
#include <stdint.h>

#define HD 128
#define NMAX 100000
#define EMAX 1600000

// ================= scratch =================
__device__ __align__(16) __half g_hf[(size_t)NMAX * HD];
__device__ __align__(16) __half g_tf[(size_t)NMAX * HD];
__device__ __align__(16) __half g_sf[(size_t)NMAX * HD];
__device__ float g_dinv[NMAX];
__device__ int   g_deg[NMAX];
__device__ int   g_off[NMAX];
__device__ int   g_cur[NMAX];
__device__ int   g_csr[EMAX];
__device__ int   g_bsums[256];
__device__ float g_gb[3 * HD];                                  // gate biases (i,g,o)
__device__ __align__(16) __half g_wf[6 * 2 * HD * HD];          // [plane][hi/lo][128*128] fp16
// planes: 0,1,2 = W_ih gate blocks (i,g,o) [n][k]; 3 = W1^T; 4 = W2^T; 5 = W3
// lo half used only for plane 5 (final GEMM insurance)

__device__ __forceinline__ uint32_t smem_u32(const void* p) {
    uint32_t a;
    asm("{ .reg .u64 t; cvta.to.shared.u64 t, %1; cvt.u32.u64 %0, t; }" : "=r"(a) : "l"(p));
    return a;
}
#define LDSM4(r, addr) \
    asm volatile("ldmatrix.sync.aligned.m8n8.x4.shared.b16 {%0,%1,%2,%3}, [%4];" \
        : "=r"((r)[0]), "=r"((r)[1]), "=r"((r)[2]), "=r"((r)[3]) : "r"(addr))

__device__ __forceinline__ void mma_f16(float* d, const uint32_t* a, const uint32_t* b) {
    asm volatile(
        "mma.sync.aligned.m16n8k16.row.col.f32.f16.f16.f32 "
        "{%0,%1,%2,%3}, {%4,%5,%6,%7}, {%8,%9}, {%0,%1,%2,%3};"
        : "+f"(d[0]), "+f"(d[1]), "+f"(d[2]), "+f"(d[3])
        : "r"(a[0]), "r"(a[1]), "r"(a[2]), "r"(a[3]), "r"(b[0]), "r"(b[1]));
}

// ================= prep: weights to fp16 (hi everywhere, lo for plane 5) =================
__global__ void prep_weights(const float* __restrict__ Wih,
                             const float* __restrict__ W1,
                             const float* __restrict__ W2,
                             const float* __restrict__ W3,
                             const float* __restrict__ bih,
                             const float* __restrict__ bhh) {
    int idx = blockIdx.x * blockDim.x + threadIdx.x;
    if (idx >= HD * HD) return;
    int nn = idx >> 7, kk = idx & 127;
    const int G[3] = {0, 256, 384};
    float src[6];
    src[0] = Wih[(G[0] + nn) * HD + kk];
    src[1] = Wih[(G[1] + nn) * HD + kk];
    src[2] = Wih[(G[2] + nn) * HD + kk];
    src[3] = W1[kk * HD + nn];
    src[4] = W2[kk * HD + nn];
    src[5] = W3[nn * HD + kk];
#pragma unroll
    for (int p = 0; p < 6; p++) {
        __half h = __float2half_rn(src[p]);
        __half l = __float2half_rn(src[p] - __half2float(h));
        g_wf[p * 32768 + idx] = h;
        g_wf[p * 32768 + 16384 + idx] = l;
    }
    if (idx < 3 * HD) {
        int p = idx / HD, j = idx % HD;
        g_gb[idx] = bih[G[p] + j] + bhh[G[p] + j];
    }
}

// ================= degree / scan / CSR =================
__global__ void zero_deg(int n) {
    int i = blockIdx.x * blockDim.x + threadIdx.x;
    if (i < n) g_deg[i] = 0;
}
__global__ void deg_count(const int* __restrict__ ei, int e) {
    int i = blockIdx.x * blockDim.x + threadIdx.x;
    if (i < e) atomicAdd(&g_deg[ei[e + i]], 1);
}
__global__ void scan1(int n) {
    __shared__ int sm[1024];
    int t = threadIdx.x, i = blockIdx.x * 1024 + t;
    int v = (i < n) ? g_deg[i] : 0;
    if (i < n) g_dinv[i] = rsqrtf((float)v + 1.0f);
    sm[t] = v; __syncthreads();
    for (int o = 1; o < 1024; o <<= 1) {
        int tmp = (t >= o) ? sm[t - o] : 0; __syncthreads();
        sm[t] += tmp; __syncthreads();
    }
    if (i < n) g_off[i] = sm[t] - v;
    if (t == 1023) g_bsums[blockIdx.x] = sm[1023];
}
__global__ void scan2(int nb) {
    __shared__ int sm[128];
    int t = threadIdx.x;
    int v = (t < nb) ? g_bsums[t] : 0;
    sm[t] = v; __syncthreads();
    for (int o = 1; o < 128; o <<= 1) {
        int tmp = (t >= o) ? sm[t - o] : 0; __syncthreads();
        sm[t] += tmp; __syncthreads();
    }
    if (t < nb) g_bsums[t] = sm[t] - v;
}
__global__ void scan3(int n) {
    int i = blockIdx.x * blockDim.x + threadIdx.x;
    if (i < n) {
        int o = g_off[i] + g_bsums[i >> 10];
        g_off[i] = o; g_cur[i] = o;
    }
}
__global__ void csr_fill(const int* __restrict__ ei, int e) {
    int i = blockIdx.x * blockDim.x + threadIdx.x;
    if (i < e) {
        int d = ei[e + i];
        g_csr[atomicAdd(&g_cur[d], 1)] = ei[i];
    }
}

// ================= fused LSTM: single-fp16 weights, full-K resident =================
#define ASTR 272          // row stride bytes (128 fp16 + pad), conflict-free
#define L_A   0           // 64  x 272 = 17408
#define L_B   17408       // 128 x 272 = 34816
#define L_TOT 52224

__global__ void __launch_bounds__(256, 3)
lstm_fused(const float* __restrict__ z, int n) {
    extern __shared__ char sm[];
    uint32_t sbase = smem_u32(sm);
    int tid = threadIdx.x, lane = tid & 31, wid = tid >> 5;
    int gid = lane >> 2, tig = lane & 3;
    int wm = wid >> 2, wn = wid & 3;            // 2 m x 4 n warps
    int r0 = blockIdx.x * 64;

    // ---- load z (fp32) -> fp16 A (64 x 128) ----
    for (int i = tid; i < 64 * 16; i += 256) {
        int row = i >> 4, q = i & 15;
        float4 v1 = make_float4(0.f, 0.f, 0.f, 0.f), v2 = v1;
        if (r0 + row < n) {
            v1 = *(const float4*)(z + (size_t)(r0 + row) * HD + q * 8);
            v2 = *(const float4*)(z + (size_t)(r0 + row) * HD + q * 8 + 4);
        }
        __half2 h0 = __float22half2_rn(make_float2(v1.x, v1.y));
        __half2 h1 = __float22half2_rn(make_float2(v1.z, v1.w));
        __half2 h2 = __float22half2_rn(make_float2(v2.x, v2.y));
        __half2 h3 = __float22half2_rn(make_float2(v2.z, v2.w));
        uint4 u = make_uint4(*(uint32_t*)&h0, *(uint32_t*)&h1, *(uint32_t*)&h2, *(uint32_t*)&h3);
        *(uint4*)(sm + L_A + row * ASTR + q * 16) = u;
    }

    uint32_t aAl = (uint32_t)((wm * 32 + (lane & 15)) * ASTR + ((lane >> 4) << 3) * 2);
    uint32_t aBl = (uint32_t)((wn * 32 + ((lane >> 4) << 3) + (lane & 7)) * ASTR
                              + ((lane >> 3) & 1) * 16);

    float cp[2][4][4];
    float acc[2][4][4];

#pragma unroll 1
    for (int p = 0; p < 3; p++) {
        __syncthreads();   // prior plane's LDSM reads done (also covers A stores, plane 0)
        // ---- load B plane p (128 x 128 fp16, hi only) ----
        for (int i = tid; i < 128 * 16; i += 256) {
            int row = i >> 4, q = i & 15;
            uint4 h = __ldg((const uint4*)(g_wf + (size_t)p * 32768 + row * HD + q * 8));
            *(uint4*)(sm + L_B + row * ASTR + q * 16) = h;
        }
        __syncthreads();

#pragma unroll
        for (int mt = 0; mt < 2; mt++)
#pragma unroll
            for (int nt = 0; nt < 4; nt++)
#pragma unroll
                for (int q = 0; q < 4; q++) acc[mt][nt][q] = 0.0f;

        uint32_t Ab = sbase + L_A + aAl;
        uint32_t Bb = sbase + L_B + aBl;
#pragma unroll
        for (int ks = 0; ks < 8; ks++) {
            uint32_t ra0[4], ra1[4], rb0[4], rb1[4];
            LDSM4(ra0, Ab + ks * 32);
            LDSM4(ra1, Ab + 16 * ASTR + ks * 32);
            LDSM4(rb0, Bb + ks * 32);
            LDSM4(rb1, Bb + 16 * ASTR + ks * 32);
            mma_f16(acc[0][0], ra0, rb0 + 0);
            mma_f16(acc[0][1], ra0, rb0 + 2);
            mma_f16(acc[0][2], ra0, rb1 + 0);
            mma_f16(acc[0][3], ra0, rb1 + 2);
            mma_f16(acc[1][0], ra1, rb0 + 0);
            mma_f16(acc[1][1], ra1, rb0 + 2);
            mma_f16(acc[1][2], ra1, rb1 + 0);
            mma_f16(acc[1][3], ra1, rb1 + 2);
        }

        // ---- plane epilogue (registers only) ----
#pragma unroll
        for (int mt = 0; mt < 2; mt++) {
#pragma unroll
            for (int nt = 0; nt < 4; nt++) {
                int col = wn * 32 + nt * 8 + tig * 2;
                float2 bg = *(const float2*)(g_gb + p * HD + col);
#pragma unroll
                for (int q = 0; q < 4; q++) {
                    float gv = acc[mt][nt][q] + ((q & 1) ? bg.y : bg.x);
                    if (p == 0)      cp[mt][nt][q] = 1.0f / (1.0f + __expf(-gv));
                    else if (p == 1) cp[mt][nt][q] = cp[mt][nt][q] * tanhf(gv);
                    else             cp[mt][nt][q] = (1.0f / (1.0f + __expf(-gv))) * tanhf(cp[mt][nt][q]);
                }
            }
        }
    }

    // ---- store h as fp16 ----
#pragma unroll
    for (int mt = 0; mt < 2; mt++) {
        int row0 = r0 + wm * 32 + mt * 16 + gid;
        int row1 = row0 + 8;
#pragma unroll
        for (int nt = 0; nt < 4; nt++) {
            int col = wn * 32 + nt * 8 + tig * 2;
            __half2 v0 = __float22half2_rn(make_float2(cp[mt][nt][0], cp[mt][nt][1]));
            __half2 v1 = __float22half2_rn(make_float2(cp[mt][nt][2], cp[mt][nt][3]));
            if (row0 < n) *(uint32_t*)(g_hf + (size_t)row0 * HD + col) = *(uint32_t*)&v0;
            if (row1 < n) *(uint32_t*)(g_hf + (size_t)row1 * HD + col) = *(uint32_t*)&v1;
        }
    }
}

// ================= mma GEMM, full-K resident, NSPLIT in {1,2} =================
// MODE 1: t = acc * dinv[row] -> fp16 C16;  MODE 2: out = relu(acc + bias[col]) -> fp32
#define G_A   0           // 128 x 272 = 34816
#define G_B   34816
#define G_B2  69632
#define SMEM_G1 69632
#define SMEM_G2 104448

template <int MODE, int NSPLIT>
__global__ void __launch_bounds__(256, 2)
mma_gemm(const __half* __restrict__ A, const __half* __restrict__ Bp,
         const float* __restrict__ bias, const float* __restrict__ dinv,
         __half* __restrict__ C16, float* __restrict__ C32, int n) {
    extern __shared__ char sm[];
    uint32_t sbase = smem_u32(sm);

    int tid = threadIdx.x, lane = tid & 31, wid = tid >> 5;
    int gid = lane >> 2, tig = lane & 3;
    int wm = wid & 3, wn = wid >> 2;
    int r0 = blockIdx.x * 128;

    uint32_t aAl = (uint32_t)((wm * 32 + (lane & 15)) * ASTR + ((lane >> 4) << 3) * 2);
    uint32_t aBl = (uint32_t)((wn * 64 + ((lane >> 4) << 3) + (lane & 7)) * ASTR
                              + ((lane >> 3) & 1) * 16);

    float acc[2][8][4];
#pragma unroll
    for (int mt = 0; mt < 2; mt++)
#pragma unroll
        for (int nt = 0; nt < 8; nt++)
#pragma unroll
            for (int q = 0; q < 4; q++) acc[mt][nt][q] = 0.0f;

    // ---- load A (128 x 128 fp16) + B hi (+ lo) ----
    for (int i = tid; i < 128 * 16; i += 256) {
        int row = i >> 4, q = i & 15;
        uint4 u = make_uint4(0u, 0u, 0u, 0u);
        if (r0 + row < n)
            u = *(const uint4*)(A + (size_t)(r0 + row) * HD + q * 8);
        *(uint4*)(sm + G_A + row * ASTR + q * 16) = u;
        uint4 h = __ldg((const uint4*)(Bp + (size_t)row * HD + q * 8));
        *(uint4*)(sm + G_B + row * ASTR + q * 16) = h;
        if (NSPLIT == 2) {
            uint4 l = __ldg((const uint4*)(Bp + 16384 + (size_t)row * HD + q * 8));
            *(uint4*)(sm + G_B2 + row * ASTR + q * 16) = l;
        }
    }
    __syncthreads();

#pragma unroll
    for (int ks = 0; ks < 8; ks++) {
        uint32_t ra0[4], ra1[4];
        LDSM4(ra0, sbase + G_A + aAl + ks * 32);
        LDSM4(ra1, sbase + G_A + aAl + 16 * ASTR + ks * 32);
#pragma unroll
        for (int s = 0; s < NSPLIT; s++) {
            uint32_t Bb = sbase + ((s == 1) ? G_B2 : G_B) + aBl + ks * 32;
#pragma unroll
            for (int nt2 = 0; nt2 < 4; nt2++) {
                uint32_t rb[4];
                LDSM4(rb, Bb + nt2 * 16 * ASTR);
                mma_f16(acc[0][nt2 * 2 + 0], ra0, rb + 0);
                mma_f16(acc[0][nt2 * 2 + 1], ra0, rb + 2);
                mma_f16(acc[1][nt2 * 2 + 0], ra1, rb + 0);
                mma_f16(acc[1][nt2 * 2 + 1], ra1, rb + 2);
            }
        }
    }

#pragma unroll
    for (int mt = 0; mt < 2; mt++) {
        int row0 = r0 + wm * 32 + mt * 16 + gid;
        int row1 = row0 + 8;
        float dv0 = 0.f, dv1 = 0.f;
        if (MODE == 1) {
            dv0 = (row0 < n) ? dinv[row0] : 0.f;
            dv1 = (row1 < n) ? dinv[row1] : 0.f;
        }
#pragma unroll
        for (int nt = 0; nt < 8; nt++) {
            int col = wn * 64 + nt * 8 + tig * 2;
            float d0 = acc[mt][nt][0], d1 = acc[mt][nt][1];
            float d2 = acc[mt][nt][2], d3 = acc[mt][nt][3];
            if (MODE == 1) {
                __half2 v0 = __float22half2_rn(make_float2(d0 * dv0, d1 * dv0));
                __half2 v1 = __float22half2_rn(make_float2(d2 * dv1, d3 * dv1));
                if (row0 < n) *(uint32_t*)(C16 + (size_t)row0 * HD + col) = *(uint32_t*)&v0;
                if (row1 < n) *(uint32_t*)(C16 + (size_t)row1 * HD + col) = *(uint32_t*)&v1;
            } else {
                float b0 = __ldg(bias + col), b1 = __ldg(bias + col + 1);
                if (row0 < n) *(float2*)(C32 + (size_t)row0 * HD + col) =
                    make_float2(fmaxf(d0 + b0, 0.f), fmaxf(d1 + b1, 0.f));
                if (row1 < n) *(float2*)(C32 + (size_t)row1 * HD + col) =
                    make_float2(fmaxf(d2 + b0, 0.f), fmaxf(d3 + b1, 0.f));
            }
        }
    }
}

// ================= CSR aggregation, fp16 in/out, fp32 accum =================
template <bool RELU>
__global__ void aggregate_k(const __half* __restrict__ t2,
                            const float* __restrict__ bias,
                            __half* __restrict__ out, int n) {
    int w = (blockIdx.x * blockDim.x + threadIdx.x) >> 5;
    int lane = threadIdx.x & 31;
    if (w >= n) return;
    const uint2* T = (const uint2*)t2;
    uint2 self = T[(size_t)w * 32 + lane];
    float2 a0 = __half22float2(*(__half2*)&self.x);
    float2 a1 = __half22float2(*(__half2*)&self.y);
    float4 acc = make_float4(a0.x, a0.y, a1.x, a1.y);
    const int* idx = g_csr + g_off[w];
    int cnt = g_deg[w];
    int i = 0;
    for (; i + 7 < cnt; i += 8) {
        int ix[8];
#pragma unroll
        for (int u = 0; u < 8; u++) ix[u] = idx[i + u];
        uint2 v[8];
#pragma unroll
        for (int u = 0; u < 8; u++) v[u] = T[(size_t)ix[u] * 32 + lane];
#pragma unroll
        for (int u = 0; u < 8; u++) {
            float2 f0 = __half22float2(*(__half2*)&v[u].x);
            float2 f1 = __half22float2(*(__half2*)&v[u].y);
            acc.x += f0.x; acc.y += f0.y; acc.z += f1.x; acc.w += f1.y;
        }
    }
    for (; i < cnt; i++) {
        uint2 v = T[(size_t)idx[i] * 32 + lane];
        float2 f0 = __half22float2(*(__half2*)&v.x);
        float2 f1 = __half22float2(*(__half2*)&v.y);
        acc.x += f0.x; acc.y += f0.y; acc.z += f1.x; acc.w += f1.y;
    }
    float dvv = g_dinv[w];
    float4 b4 = ((const float4*)bias)[lane];
    float o0 = acc.x * dvv + b4.x, o1 = acc.y * dvv + b4.y;
    float o2 = acc.z * dvv + b4.z, o3 = acc.w * dvv + b4.w;
    if (RELU) {
        o0 = fmaxf(o0, 0.f); o1 = fmaxf(o1, 0.f);
        o2 = fmaxf(o2, 0.f); o3 = fmaxf(o3, 0.f);
    }
    __half2 h0 = __float22half2_rn(make_float2(o0, o1));
    __half2 h1 = __float22half2_rn(make_float2(o2, o3));
    uint2 o = make_uint2(*(uint32_t*)&h0, *(uint32_t*)&h1);
    ((uint2*)out)[(size_t)w * 32 + lane] = o;
}

// ================= launch =================
extern "C" void kernel_launch(void* const* d_in, const int* in_sizes, int n_in,
                              void* d_out, int out_size) {
    const float* z   = (const float*)d_in[0];
    const int*   ei  = (const int*)d_in[1];
    const float* Wih = (const float*)d_in[2];
    const float* bih = (const float*)d_in[4];
    const float* bhh = (const float*)d_in[5];
    const float* W1  = (const float*)d_in[6];
    const float* b1  = (const float*)d_in[7];
    const float* W2  = (const float*)d_in[8];
    const float* b2  = (const float*)d_in[9];
    const float* W3  = (const float*)d_in[10];
    const float* b3  = (const float*)d_in[11];

    int n = in_sizes[0] / HD;
    int e = in_sizes[1] / 2;
    float* out = (float*)d_out;

    __half *p_hf, *p_tf, *p_sf, *p_wf;
    float *p_dinv;
    cudaGetSymbolAddress((void**)&p_hf, g_hf);
    cudaGetSymbolAddress((void**)&p_tf, g_tf);
    cudaGetSymbolAddress((void**)&p_sf, g_sf);
    cudaGetSymbolAddress((void**)&p_wf, g_wf);
    cudaGetSymbolAddress((void**)&p_dinv, g_dinv);

    cudaFuncSetAttribute(lstm_fused, cudaFuncAttributeMaxDynamicSharedMemorySize, L_TOT);
    cudaFuncSetAttribute(mma_gemm<1, 1>, cudaFuncAttributeMaxDynamicSharedMemorySize, SMEM_G1);
    cudaFuncSetAttribute(mma_gemm<2, 2>, cudaFuncAttributeMaxDynamicSharedMemorySize, SMEM_G2);

    int nb = (n + 1023) / 1024;
    // ordering: ncu capture slot (4th launch) = lstm_fused
    prep_weights<<<(HD * HD + 255) / 256, 256>>>(Wih, W1, W2, W3, bih, bhh);   // 1
    zero_deg<<<(n + 255) / 256, 256>>>(n);                                     // 2
    deg_count<<<(e + 255) / 256, 256>>>(ei, e);                                // 3
    lstm_fused<<<(n + 63) / 64, 256, L_TOT>>>(z, n);                           // 4 <- profiled
    scan1<<<nb, 1024>>>(n);
    scan2<<<1, 128>>>(nb);
    scan3<<<(n + 255) / 256, 256>>>(n);
    csr_fill<<<(e + 255) / 256, 256>>>(ei, e);

    dim3 gg((n + 127) / 128);
    // conv1 transform: t = (h @ W1) * dinv[row]   (fp16 out, single-split)
    mma_gemm<1, 1><<<gg, 256, SMEM_G1>>>(p_hf, p_wf + 3 * 32768, nullptr, p_dinv, p_tf, nullptr, n);
    // conv1 aggregate + fused relu: s = relu(dinv*(t+sum)+b1)
    aggregate_k<true><<<((size_t)n * 32 + 255) / 256, 256>>>(p_tf, b1, p_sf, n);
    // conv2 transform: t = (s @ W2) * dinv[row]   (relu already applied)
    mma_gemm<1, 1><<<gg, 256, SMEM_G1>>>(p_sf, p_wf + 4 * 32768, nullptr, p_dinv, p_tf, nullptr, n);
    aggregate_k<false><<<((size_t)n * 32 + 255) / 256, 256>>>(p_tf, b2, p_sf, n);
    // final: out = relu(s @ W3^T + b3)  (fp32 out, hi/lo split for accuracy)
    mma_gemm<2, 2><<<gg, 256, SMEM_G2>>>(p_sf, p_wf + 5 * 32768, b3, nullptr, nullptr, out, n);
}

// round 13
// speedup vs baseline: 1.9159x; 1.1118x over previous
#include <cuda_runtime.h>
#include <cuda_fp16.h>
#include <math.h>
#include <stdint.h>

#define HD 128
#define NMAX 100000
#define EMAX 1600000

// ================= scratch =================
__device__ __align__(16) __half g_tf[(size_t)NMAX * HD];
__device__ __align__(16) __half g_sf[(size_t)NMAX * HD];
__device__ float g_dinv[NMAX];
__device__ int   g_deg[NMAX];
__device__ int   g_off[NMAX];
__device__ int   g_cur[NMAX];
__device__ int   g_csr[EMAX];
__device__ int   g_bsums[256];
__device__ float g_gb[3 * HD];                          // gate biases (i,g,o)
__device__ __align__(16) __half g_wf[6 * HD * HD];      // fp16 weight planes [n][k]
// 0,1,2 = W_ih gate blocks (i,g,o); 3 = W1^T; 4 = W2^T; 5 = W3

__device__ __forceinline__ uint32_t smem_u32(const void* p) {
    uint32_t a;
    asm("{ .reg .u64 t; cvta.to.shared.u64 t, %1; cvt.u32.u64 %0, t; }" : "=r"(a) : "l"(p));
    return a;
}
#define LDSM4(r, addr) \
    asm volatile("ldmatrix.sync.aligned.m8n8.x4.shared.b16 {%0,%1,%2,%3}, [%4];" \
        : "=r"((r)[0]), "=r"((r)[1]), "=r"((r)[2]), "=r"((r)[3]) : "r"(addr))

__device__ __forceinline__ void mma_f16(float* d, const uint32_t* a, const uint32_t* b) {
    asm volatile(
        "mma.sync.aligned.m16n8k16.row.col.f32.f16.f16.f32 "
        "{%0,%1,%2,%3}, {%4,%5,%6,%7}, {%8,%9}, {%0,%1,%2,%3};"
        : "+f"(d[0]), "+f"(d[1]), "+f"(d[2]), "+f"(d[3])
        : "r"(a[0]), "r"(a[1]), "r"(a[2]), "r"(a[3]), "r"(b[0]), "r"(b[1]));
}

// ================= prep: weights -> fp16; also zero g_deg =================
__global__ void prep_zero(const float* __restrict__ Wih,
                          const float* __restrict__ W1,
                          const float* __restrict__ W2,
                          const float* __restrict__ W3,
                          const float* __restrict__ bih,
                          const float* __restrict__ bhh, int n) {
    int idx = blockIdx.x * blockDim.x + threadIdx.x;
    if (idx < n) g_deg[idx] = 0;
    if (idx < HD * HD) {
        int nn = idx >> 7, kk = idx & 127;
        const int G[3] = {0, 256, 384};
        g_wf[0 * 16384 + idx] = __float2half_rn(Wih[(G[0] + nn) * HD + kk]);
        g_wf[1 * 16384 + idx] = __float2half_rn(Wih[(G[1] + nn) * HD + kk]);
        g_wf[2 * 16384 + idx] = __float2half_rn(Wih[(G[2] + nn) * HD + kk]);
        g_wf[3 * 16384 + idx] = __float2half_rn(W1[kk * HD + nn]);
        g_wf[4 * 16384 + idx] = __float2half_rn(W2[kk * HD + nn]);
        g_wf[5 * 16384 + idx] = __float2half_rn(W3[nn * HD + kk]);
        if (idx < 3 * HD) {
            int p = idx / HD, j = idx % HD;
            g_gb[idx] = bih[G[p] + j] + bhh[G[p] + j];
        }
    }
}

// ================= degree / scan / CSR =================
__global__ void deg_count(const int* __restrict__ ei, int e) {
    int i = blockIdx.x * blockDim.x + threadIdx.x;
    if (i < e) atomicAdd(&g_deg[ei[e + i]], 1);
}
__global__ void scan1(int n) {
    __shared__ int sm[1024];
    int t = threadIdx.x, i = blockIdx.x * 1024 + t;
    int v = (i < n) ? g_deg[i] : 0;
    if (i < n) g_dinv[i] = rsqrtf((float)v + 1.0f);
    sm[t] = v; __syncthreads();
    for (int o = 1; o < 1024; o <<= 1) {
        int tmp = (t >= o) ? sm[t - o] : 0; __syncthreads();
        sm[t] += tmp; __syncthreads();
    }
    if (i < n) g_off[i] = sm[t] - v;
    if (t == 1023) g_bsums[blockIdx.x] = sm[1023];
}
__global__ void scan2(int nb) {
    __shared__ int sm[128];
    int t = threadIdx.x;
    int v = (t < nb) ? g_bsums[t] : 0;
    sm[t] = v; __syncthreads();
    for (int o = 1; o < 128; o <<= 1) {
        int tmp = (t >= o) ? sm[t - o] : 0; __syncthreads();
        sm[t] += tmp; __syncthreads();
    }
    if (t < nb) g_bsums[t] = sm[t] - v;
}
__global__ void scan3(int n) {
    int i = blockIdx.x * blockDim.x + threadIdx.x;
    if (i < n) {
        int o = g_off[i] + g_bsums[i >> 10];
        g_off[i] = o; g_cur[i] = o;
    }
}
__global__ void csr_fill(const int* __restrict__ ei, int e) {
    int i = blockIdx.x * blockDim.x + threadIdx.x;
    if (i < e) {
        int d = ei[e + i];
        g_csr[atomicAdd(&g_cur[d], 1)] = ei[i];
    }
}

// ================= fused LSTM + conv1 transform =================
// planes 0-2: gates -> h (registers); plane 3: t = (h @ W1) * dinv -> g_tf
#define ASTR 272          // row stride bytes (128 fp16 + pad), conflict-free
#define L_A   0           // 64  x 272 = 17408
#define L_B   17408       // 128 x 272 = 34816
#define L_TOT 52224

__global__ void __launch_bounds__(256, 3)
lstm_fused(const float* __restrict__ z, const float* __restrict__ dinv,
           __half* __restrict__ tout, int n) {
    extern __shared__ char sm[];
    uint32_t sbase = smem_u32(sm);
    int tid = threadIdx.x, lane = tid & 31, wid = tid >> 5;
    int gid = lane >> 2, tig = lane & 3;
    int wm = wid >> 2, wn = wid & 3;            // 2 m x 4 n warps
    int r0 = blockIdx.x * 64;

    // ---- load z (fp32) -> fp16 A (64 x 128) ----
    for (int i = tid; i < 64 * 16; i += 256) {
        int row = i >> 4, q = i & 15;
        float4 v1 = make_float4(0.f, 0.f, 0.f, 0.f), v2 = v1;
        if (r0 + row < n) {
            v1 = *(const float4*)(z + (size_t)(r0 + row) * HD + q * 8);
            v2 = *(const float4*)(z + (size_t)(r0 + row) * HD + q * 8 + 4);
        }
        __half2 h0 = __float22half2_rn(make_float2(v1.x, v1.y));
        __half2 h1 = __float22half2_rn(make_float2(v1.z, v1.w));
        __half2 h2 = __float22half2_rn(make_float2(v2.x, v2.y));
        __half2 h3 = __float22half2_rn(make_float2(v2.z, v2.w));
        uint4 u = make_uint4(*(uint32_t*)&h0, *(uint32_t*)&h1, *(uint32_t*)&h2, *(uint32_t*)&h3);
        *(uint4*)(sm + L_A + row * ASTR + q * 16) = u;
    }

    uint32_t aAl = (uint32_t)((wm * 32 + (lane & 15)) * ASTR + ((lane >> 4) << 3) * 2);
    uint32_t aBl = (uint32_t)((wn * 32 + ((lane >> 4) << 3) + (lane & 7)) * ASTR
                              + ((lane >> 3) & 1) * 16);

    float cp[2][4][4];
    float acc[2][4][4];

#pragma unroll 1
    for (int p = 0; p < 4; p++) {
        __syncthreads();   // prior plane's LDSM reads done (covers A stores at p=0)
        if (p == 3) {
            // h (registers) -> A buffer as fp16; conflict-free (banks row*4+tig)
#pragma unroll
            for (int mt = 0; mt < 2; mt++) {
#pragma unroll
                for (int nt = 0; nt < 4; nt++) {
                    int col = wn * 32 + nt * 8 + tig * 2;
                    int ra = wm * 32 + mt * 16 + gid;
                    __half2 v0 = __float22half2_rn(make_float2(cp[mt][nt][0], cp[mt][nt][1]));
                    __half2 v1 = __float22half2_rn(make_float2(cp[mt][nt][2], cp[mt][nt][3]));
                    *(uint32_t*)(sm + L_A + ra * ASTR + col * 2) = *(uint32_t*)&v0;
                    *(uint32_t*)(sm + L_A + (ra + 8) * ASTR + col * 2) = *(uint32_t*)&v1;
                }
            }
        }
        // ---- load B plane p (128 x 128 fp16) ----
        for (int i = tid; i < 128 * 16; i += 256) {
            int row = i >> 4, q = i & 15;
            uint4 h = __ldg((const uint4*)(g_wf + (size_t)p * 16384 + row * HD + q * 8));
            *(uint4*)(sm + L_B + row * ASTR + q * 16) = h;
        }
        __syncthreads();

#pragma unroll
        for (int mt = 0; mt < 2; mt++)
#pragma unroll
            for (int nt = 0; nt < 4; nt++)
#pragma unroll
                for (int q = 0; q < 4; q++) acc[mt][nt][q] = 0.0f;

        uint32_t Ab = sbase + L_A + aAl;
        uint32_t Bb = sbase + L_B + aBl;
#pragma unroll
        for (int ks = 0; ks < 8; ks++) {
            uint32_t ra0[4], ra1[4], rb0[4], rb1[4];
            LDSM4(ra0, Ab + ks * 32);
            LDSM4(ra1, Ab + 16 * ASTR + ks * 32);
            LDSM4(rb0, Bb + ks * 32);
            LDSM4(rb1, Bb + 16 * ASTR + ks * 32);
            mma_f16(acc[0][0], ra0, rb0 + 0);
            mma_f16(acc[0][1], ra0, rb0 + 2);
            mma_f16(acc[0][2], ra0, rb1 + 0);
            mma_f16(acc[0][3], ra0, rb1 + 2);
            mma_f16(acc[1][0], ra1, rb0 + 0);
            mma_f16(acc[1][1], ra1, rb0 + 2);
            mma_f16(acc[1][2], ra1, rb1 + 0);
            mma_f16(acc[1][3], ra1, rb1 + 2);
        }

        if (p < 3) {
            // gate epilogue (registers only)
#pragma unroll
            for (int mt = 0; mt < 2; mt++) {
#pragma unroll
                for (int nt = 0; nt < 4; nt++) {
                    int col = wn * 32 + nt * 8 + tig * 2;
                    float2 bg = *(const float2*)(g_gb + p * HD + col);
#pragma unroll
                    for (int q = 0; q < 4; q++) {
                        float gv = acc[mt][nt][q] + ((q & 1) ? bg.y : bg.x);
                        if (p == 0)      cp[mt][nt][q] = 1.0f / (1.0f + __expf(-gv));
                        else if (p == 1) cp[mt][nt][q] = cp[mt][nt][q] * tanhf(gv);
                        else             cp[mt][nt][q] = (1.0f / (1.0f + __expf(-gv))) * tanhf(cp[mt][nt][q]);
                    }
                }
            }
        } else {
            // conv1-transform epilogue: t = acc * dinv[row] -> gmem fp16
#pragma unroll
            for (int mt = 0; mt < 2; mt++) {
                int row0 = r0 + wm * 32 + mt * 16 + gid;
                int row1 = row0 + 8;
                float dv0 = (row0 < n) ? dinv[row0] : 0.f;
                float dv1 = (row1 < n) ? dinv[row1] : 0.f;
#pragma unroll
                for (int nt = 0; nt < 4; nt++) {
                    int col = wn * 32 + nt * 8 + tig * 2;
                    __half2 v0 = __float22half2_rn(make_float2(acc[mt][nt][0] * dv0, acc[mt][nt][1] * dv0));
                    __half2 v1 = __float22half2_rn(make_float2(acc[mt][nt][2] * dv1, acc[mt][nt][3] * dv1));
                    if (row0 < n) *(uint32_t*)(tout + (size_t)row0 * HD + col) = *(uint32_t*)&v0;
                    if (row1 < n) *(uint32_t*)(tout + (size_t)row1 * HD + col) = *(uint32_t*)&v1;
                }
            }
        }
    }
}

// ================= mma GEMM, full-K resident, single fp16 =================
// MODE 1: t = acc * dinv[row] -> fp16 C16;  MODE 2: out = relu(acc + bias[col]) -> fp32
#define G_A   0           // 128 x 272 = 34816
#define G_B   34816
#define SMEM_G 69632

template <int MODE>
__global__ void __launch_bounds__(256, 2)
mma_gemm(const __half* __restrict__ A, const __half* __restrict__ Bp,
         const float* __restrict__ bias, const float* __restrict__ dinv,
         __half* __restrict__ C16, float* __restrict__ C32, int n) {
    extern __shared__ char sm[];
    uint32_t sbase = smem_u32(sm);

    int tid = threadIdx.x, lane = tid & 31, wid = tid >> 5;
    int gid = lane >> 2, tig = lane & 3;
    int wm = wid & 3, wn = wid >> 2;
    int r0 = blockIdx.x * 128;

    uint32_t aAl = (uint32_t)((wm * 32 + (lane & 15)) * ASTR + ((lane >> 4) << 3) * 2);
    uint32_t aBl = (uint32_t)((wn * 64 + ((lane >> 4) << 3) + (lane & 7)) * ASTR
                              + ((lane >> 3) & 1) * 16);

    float acc[2][8][4];
#pragma unroll
    for (int mt = 0; mt < 2; mt++)
#pragma unroll
        for (int nt = 0; nt < 8; nt++)
#pragma unroll
            for (int q = 0; q < 4; q++) acc[mt][nt][q] = 0.0f;

    for (int i = tid; i < 128 * 16; i += 256) {
        int row = i >> 4, q = i & 15;
        uint4 u = make_uint4(0u, 0u, 0u, 0u);
        if (r0 + row < n)
            u = *(const uint4*)(A + (size_t)(r0 + row) * HD + q * 8);
        *(uint4*)(sm + G_A + row * ASTR + q * 16) = u;
        uint4 h = __ldg((const uint4*)(Bp + (size_t)row * HD + q * 8));
        *(uint4*)(sm + G_B + row * ASTR + q * 16) = h;
    }
    __syncthreads();

#pragma unroll
    for (int ks = 0; ks < 8; ks++) {
        uint32_t ra0[4], ra1[4];
        LDSM4(ra0, sbase + G_A + aAl + ks * 32);
        LDSM4(ra1, sbase + G_A + aAl + 16 * ASTR + ks * 32);
#pragma unroll
        for (int nt2 = 0; nt2 < 4; nt2++) {
            uint32_t rb[4];
            LDSM4(rb, sbase + G_B + aBl + nt2 * 16 * ASTR + ks * 32);
            mma_f16(acc[0][nt2 * 2 + 0], ra0, rb + 0);
            mma_f16(acc[0][nt2 * 2 + 1], ra0, rb + 2);
            mma_f16(acc[1][nt2 * 2 + 0], ra1, rb + 0);
            mma_f16(acc[1][nt2 * 2 + 1], ra1, rb + 2);
        }
    }

#pragma unroll
    for (int mt = 0; mt < 2; mt++) {
        int row0 = r0 + wm * 32 + mt * 16 + gid;
        int row1 = row0 + 8;
        float dv0 = 0.f, dv1 = 0.f;
        if (MODE == 1) {
            dv0 = (row0 < n) ? dinv[row0] : 0.f;
            dv1 = (row1 < n) ? dinv[row1] : 0.f;
        }
#pragma unroll
        for (int nt = 0; nt < 8; nt++) {
            int col = wn * 64 + nt * 8 + tig * 2;
            float d0 = acc[mt][nt][0], d1 = acc[mt][nt][1];
            float d2 = acc[mt][nt][2], d3 = acc[mt][nt][3];
            if (MODE == 1) {
                __half2 v0 = __float22half2_rn(make_float2(d0 * dv0, d1 * dv0));
                __half2 v1 = __float22half2_rn(make_float2(d2 * dv1, d3 * dv1));
                if (row0 < n) *(uint32_t*)(C16 + (size_t)row0 * HD + col) = *(uint32_t*)&v0;
                if (row1 < n) *(uint32_t*)(C16 + (size_t)row1 * HD + col) = *(uint32_t*)&v1;
            } else {
                float b0 = __ldg(bias + col), b1 = __ldg(bias + col + 1);
                if (row0 < n) *(float2*)(C32 + (size_t)row0 * HD + col) =
                    make_float2(fmaxf(d0 + b0, 0.f), fmaxf(d1 + b1, 0.f));
                if (row1 < n) *(float2*)(C32 + (size_t)row1 * HD + col) =
                    make_float2(fmaxf(d2 + b0, 0.f), fmaxf(d3 + b1, 0.f));
            }
        }
    }
}

// ================= CSR aggregation, fp16 in/out, fp32 accum =================
template <bool RELU>
__global__ void aggregate_k(const __half* __restrict__ t2,
                            const float* __restrict__ bias,
                            __half* __restrict__ out, int n) {
    int w = (blockIdx.x * blockDim.x + threadIdx.x) >> 5;
    int lane = threadIdx.x & 31;
    if (w >= n) return;
    const uint2* T = (const uint2*)t2;
    uint2 self = T[(size_t)w * 32 + lane];
    float2 a0 = __half22float2(*(__half2*)&self.x);
    float2 a1 = __half22float2(*(__half2*)&self.y);
    float4 acc = make_float4(a0.x, a0.y, a1.x, a1.y);
    const int* idx = g_csr + g_off[w];
    int cnt = g_deg[w];
    int i = 0;
    for (; i + 7 < cnt; i += 8) {
        int ix[8];
#pragma unroll
        for (int u = 0; u < 8; u++) ix[u] = idx[i + u];
        uint2 v[8];
#pragma unroll
        for (int u = 0; u < 8; u++) v[u] = T[(size_t)ix[u] * 32 + lane];
#pragma unroll
        for (int u = 0; u < 8; u++) {
            float2 f0 = __half22float2(*(__half2*)&v[u].x);
            float2 f1 = __half22float2(*(__half2*)&v[u].y);
            acc.x += f0.x; acc.y += f0.y; acc.z += f1.x; acc.w += f1.y;
        }
    }
    for (; i < cnt; i++) {
        uint2 v = T[(size_t)idx[i] * 32 + lane];
        float2 f0 = __half22float2(*(__half2*)&v.x);
        float2 f1 = __half22float2(*(__half2*)&v.y);
        acc.x += f0.x; acc.y += f0.y; acc.z += f1.x; acc.w += f1.y;
    }
    float dvv = g_dinv[w];
    float4 b4 = ((const float4*)bias)[lane];
    float o0 = acc.x * dvv + b4.x, o1 = acc.y * dvv + b4.y;
    float o2 = acc.z * dvv + b4.z, o3 = acc.w * dvv + b4.w;
    if (RELU) {
        o0 = fmaxf(o0, 0.f); o1 = fmaxf(o1, 0.f);
        o2 = fmaxf(o2, 0.f); o3 = fmaxf(o3, 0.f);
    }
    __half2 h0 = __float22half2_rn(make_float2(o0, o1));
    __half2 h1 = __float22half2_rn(make_float2(o2, o3));
    uint2 o = make_uint2(*(uint32_t*)&h0, *(uint32_t*)&h1);
    ((uint2*)out)[(size_t)w * 32 + lane] = o;
}

// ================= launch =================
extern "C" void kernel_launch(void* const* d_in, const int* in_sizes, int n_in,
                              void* d_out, int out_size) {
    const float* z   = (const float*)d_in[0];
    const int*   ei  = (const int*)d_in[1];
    const float* Wih = (const float*)d_in[2];
    const float* bih = (const float*)d_in[4];
    const float* bhh = (const float*)d_in[5];
    const float* W1  = (const float*)d_in[6];
    const float* b1  = (const float*)d_in[7];
    const float* W2  = (const float*)d_in[8];
    const float* b2  = (const float*)d_in[9];
    const float* W3  = (const float*)d_in[10];
    const float* b3  = (const float*)d_in[11];

    int n = in_sizes[0] / HD;
    int e = in_sizes[1] / 2;
    float* out = (float*)d_out;

    __half *p_tf, *p_sf, *p_wf;
    float *p_dinv;
    cudaGetSymbolAddress((void**)&p_tf, g_tf);
    cudaGetSymbolAddress((void**)&p_sf, g_sf);
    cudaGetSymbolAddress((void**)&p_wf, g_wf);
    cudaGetSymbolAddress((void**)&p_dinv, g_dinv);

    cudaFuncSetAttribute(lstm_fused, cudaFuncAttributeMaxDynamicSharedMemorySize, L_TOT);
    cudaFuncSetAttribute(mma_gemm<1>, cudaFuncAttributeMaxDynamicSharedMemorySize, SMEM_G);
    cudaFuncSetAttribute(mma_gemm<2>, cudaFuncAttributeMaxDynamicSharedMemorySize, SMEM_G);

    int nb = (n + 1023) / 1024;
    // ordering: ncu capture slot (4th launch) = lstm_fused
    prep_zero<<<(n + 255) / 256, 256>>>(Wih, W1, W2, W3, bih, bhh, n);          // 1
    deg_count<<<(e + 255) / 256, 256>>>(ei, e);                                  // 2
    scan1<<<nb, 1024>>>(n);                                                      // 3 (dinv ready)
    lstm_fused<<<(n + 63) / 64, 256, L_TOT>>>(z, p_dinv, p_tf, n);               // 4 <- profiled
    scan2<<<1, 128>>>(nb);                                                       // 5
    scan3<<<(n + 255) / 256, 256>>>(n);                                          // 6
    csr_fill<<<(e + 255) / 256, 256>>>(ei, e);                                   // 7

    dim3 gg((n + 127) / 128);
    // conv1 aggregate + fused relu: s = relu(dinv*(t+sum)+b1)
    aggregate_k<true><<<((size_t)n * 32 + 255) / 256, 256>>>(p_tf, b1, p_sf, n);
    // conv2 transform: t = (s @ W2) * dinv[row]
    mma_gemm<1><<<gg, 256, SMEM_G>>>(p_sf, p_wf + 4 * 16384, nullptr, p_dinv, p_tf, nullptr, n);
    aggregate_k<false><<<((size_t)n * 32 + 255) / 256, 256>>>(p_tf, b2, p_sf, n);
    // final: out = relu(s @ W3^T + b3)
    mma_gemm<2><<<gg, 256, SMEM_G>>>(p_sf, p_wf + 5 * 16384, b3, nullptr, nullptr, out, n);
}

// round 14
// speedup vs baseline: 2.0853x; 1.0884x over previous
#include <cuda_runtime.h>
#include <cuda_fp16.h>
#include <math.h>
#include <stdint.h>

#define HD 128
#define NMAX 100000
#define EMAX 1600000

// ================= scratch =================
__device__ __align__(16) __half g_tf[(size_t)NMAX * HD];
__device__ __align__(16) __half g_sf[(size_t)NMAX * HD];
__device__ float g_dinv[NMAX];
__device__ int   g_deg[NMAX];
__device__ int   g_off[NMAX];
__device__ int   g_cur[NMAX];
__device__ int   g_csr[EMAX];
__device__ int   g_base;                                // scan ticket counter
__device__ float g_gb[3 * HD];                          // gate biases (i,g,o)
__device__ __align__(16) __half g_wf[6 * HD * HD];      // fp16 weight planes [n][k]
// 0,1,2 = W_ih gate blocks (i,g,o); 3 = W1^T; 4 = W2^T; 5 = W3

__device__ __forceinline__ uint32_t smem_u32(const void* p) {
    uint32_t a;
    asm("{ .reg .u64 t; cvta.to.shared.u64 t, %1; cvt.u32.u64 %0, t; }" : "=r"(a) : "l"(p));
    return a;
}
#define LDSM4(r, addr) \
    asm volatile("ldmatrix.sync.aligned.m8n8.x4.shared.b16 {%0,%1,%2,%3}, [%4];" \
        : "=r"((r)[0]), "=r"((r)[1]), "=r"((r)[2]), "=r"((r)[3]) : "r"(addr))

__device__ __forceinline__ void mma_f16(float* d, const uint32_t* a, const uint32_t* b) {
    asm volatile(
        "mma.sync.aligned.m16n8k16.row.col.f32.f16.f16.f32 "
        "{%0,%1,%2,%3}, {%4,%5,%6,%7}, {%8,%9}, {%0,%1,%2,%3};"
        : "+f"(d[0]), "+f"(d[1]), "+f"(d[2]), "+f"(d[3])
        : "r"(a[0]), "r"(a[1]), "r"(a[2]), "r"(a[3]), "r"(b[0]), "r"(b[1]));
}

// fast activations: MUFU-based, rel err ~2^-21 (numerically safe)
__device__ __forceinline__ float fsig(float x)  { return __fdividef(1.0f, 1.0f + __expf(-x)); }
__device__ __forceinline__ float ftanh(float x) { return __fdividef(2.0f, 1.0f + __expf(-2.0f * x)) - 1.0f; }

// ================= prep: weights -> fp16; zero deg + ticket =================
__global__ void prep_zero(const float* __restrict__ Wih,
                          const float* __restrict__ W1,
                          const float* __restrict__ W2,
                          const float* __restrict__ W3,
                          const float* __restrict__ bih,
                          const float* __restrict__ bhh, int n) {
    int idx = blockIdx.x * blockDim.x + threadIdx.x;
    if (idx == 0) g_base = 0;
    if (idx < n) g_deg[idx] = 0;
    if (idx < HD * HD) {
        int nn = idx >> 7, kk = idx & 127;
        const int G[3] = {0, 256, 384};
        g_wf[0 * 16384 + idx] = __float2half_rn(Wih[(G[0] + nn) * HD + kk]);
        g_wf[1 * 16384 + idx] = __float2half_rn(Wih[(G[1] + nn) * HD + kk]);
        g_wf[2 * 16384 + idx] = __float2half_rn(Wih[(G[2] + nn) * HD + kk]);
        g_wf[3 * 16384 + idx] = __float2half_rn(W1[kk * HD + nn]);
        g_wf[4 * 16384 + idx] = __float2half_rn(W2[kk * HD + nn]);
        g_wf[5 * 16384 + idx] = __float2half_rn(W3[nn * HD + kk]);
        if (idx < 3 * HD) {
            int p = idx / HD, j = idx % HD;
            g_gb[idx] = bih[G[p] + j] + bhh[G[p] + j];
        }
    }
}

// ================= degree / single-pass scan / CSR =================
__global__ void deg_count(const int* __restrict__ ei, int e) {
    int i = blockIdx.x * blockDim.x + threadIdx.x;
    if (i < e) atomicAdd(&g_deg[ei[e + i]], 1);
}
// block-local scan + atomic ticket base (CSR needs disjoint segments, not ordered prefix)
__global__ void scan_k(int n) {
    __shared__ int sm[1024];
    __shared__ int sbase;
    int t = threadIdx.x, i = blockIdx.x * 1024 + t;
    int v = (i < n) ? g_deg[i] : 0;
    if (i < n) g_dinv[i] = rsqrtf((float)v + 1.0f);
    sm[t] = v; __syncthreads();
    for (int o = 1; o < 1024; o <<= 1) {
        int tmp = (t >= o) ? sm[t - o] : 0; __syncthreads();
        sm[t] += tmp; __syncthreads();
    }
    if (t == 1023) sbase = atomicAdd(&g_base, sm[1023]);
    __syncthreads();
    if (i < n) {
        int o = sm[t] - v + sbase;
        g_off[i] = o; g_cur[i] = o;
    }
}
__global__ void csr_fill(const int* __restrict__ ei, int e) {
    int i = blockIdx.x * blockDim.x + threadIdx.x;
    if (i < e) {
        int d = ei[e + i];
        g_csr[atomicAdd(&g_cur[d], 1)] = ei[i];
    }
}

// ================= fused LSTM + conv1 transform =================
// planes 0-2: gates -> h (registers); plane 3: t = (h @ W1) * dinv -> g_tf
#define ASTR 272          // row stride bytes (128 fp16 + pad), conflict-free
#define L_A   0           // 64  x 272 = 17408
#define L_B   17408       // 128 x 272 = 34816
#define L_TOT 52224

__global__ void __launch_bounds__(256, 3)
lstm_fused(const float* __restrict__ z, const float* __restrict__ dinv,
           __half* __restrict__ tout, int n) {
    extern __shared__ char sm[];
    uint32_t sbase = smem_u32(sm);
    int tid = threadIdx.x, lane = tid & 31, wid = tid >> 5;
    int gid = lane >> 2, tig = lane & 3;
    int wm = wid >> 2, wn = wid & 3;            // 2 m x 4 n warps
    int r0 = blockIdx.x * 64;

    // ---- load z (fp32) -> fp16 A (64 x 128) ----
    for (int i = tid; i < 64 * 16; i += 256) {
        int row = i >> 4, q = i & 15;
        float4 v1 = make_float4(0.f, 0.f, 0.f, 0.f), v2 = v1;
        if (r0 + row < n) {
            v1 = *(const float4*)(z + (size_t)(r0 + row) * HD + q * 8);
            v2 = *(const float4*)(z + (size_t)(r0 + row) * HD + q * 8 + 4);
        }
        __half2 h0 = __float22half2_rn(make_float2(v1.x, v1.y));
        __half2 h1 = __float22half2_rn(make_float2(v1.z, v1.w));
        __half2 h2 = __float22half2_rn(make_float2(v2.x, v2.y));
        __half2 h3 = __float22half2_rn(make_float2(v2.z, v2.w));
        uint4 u = make_uint4(*(uint32_t*)&h0, *(uint32_t*)&h1, *(uint32_t*)&h2, *(uint32_t*)&h3);
        *(uint4*)(sm + L_A + row * ASTR + q * 16) = u;
    }

    uint32_t aAl = (uint32_t)((wm * 32 + (lane & 15)) * ASTR + ((lane >> 4) << 3) * 2);
    uint32_t aBl = (uint32_t)((wn * 32 + ((lane >> 4) << 3) + (lane & 7)) * ASTR
                              + ((lane >> 3) & 1) * 16);

    float cp[2][4][4];
    float acc[2][4][4];

#pragma unroll 1
    for (int p = 0; p < 4; p++) {
        __syncthreads();   // prior plane's LDSM reads done (covers A stores at p=0)
        if (p == 3) {
            // h (registers) -> A buffer as fp16
#pragma unroll
            for (int mt = 0; mt < 2; mt++) {
#pragma unroll
                for (int nt = 0; nt < 4; nt++) {
                    int col = wn * 32 + nt * 8 + tig * 2;
                    int ra = wm * 32 + mt * 16 + gid;
                    __half2 v0 = __float22half2_rn(make_float2(cp[mt][nt][0], cp[mt][nt][1]));
                    __half2 v1 = __float22half2_rn(make_float2(cp[mt][nt][2], cp[mt][nt][3]));
                    *(uint32_t*)(sm + L_A + ra * ASTR + col * 2) = *(uint32_t*)&v0;
                    *(uint32_t*)(sm + L_A + (ra + 8) * ASTR + col * 2) = *(uint32_t*)&v1;
                }
            }
        }
        // ---- load B plane p (128 x 128 fp16) ----
        for (int i = tid; i < 128 * 16; i += 256) {
            int row = i >> 4, q = i & 15;
            uint4 h = __ldg((const uint4*)(g_wf + (size_t)p * 16384 + row * HD + q * 8));
            *(uint4*)(sm + L_B + row * ASTR + q * 16) = h;
        }
        __syncthreads();

#pragma unroll
        for (int mt = 0; mt < 2; mt++)
#pragma unroll
            for (int nt = 0; nt < 4; nt++)
#pragma unroll
                for (int q = 0; q < 4; q++) acc[mt][nt][q] = 0.0f;

        uint32_t Ab = sbase + L_A + aAl;
        uint32_t Bb = sbase + L_B + aBl;
#pragma unroll
        for (int ks = 0; ks < 8; ks++) {
            uint32_t ra0[4], ra1[4], rb0[4], rb1[4];
            LDSM4(ra0, Ab + ks * 32);
            LDSM4(ra1, Ab + 16 * ASTR + ks * 32);
            LDSM4(rb0, Bb + ks * 32);
            LDSM4(rb1, Bb + 16 * ASTR + ks * 32);
            mma_f16(acc[0][0], ra0, rb0 + 0);
            mma_f16(acc[0][1], ra0, rb0 + 2);
            mma_f16(acc[0][2], ra0, rb1 + 0);
            mma_f16(acc[0][3], ra0, rb1 + 2);
            mma_f16(acc[1][0], ra1, rb0 + 0);
            mma_f16(acc[1][1], ra1, rb0 + 2);
            mma_f16(acc[1][2], ra1, rb1 + 0);
            mma_f16(acc[1][3], ra1, rb1 + 2);
        }

        if (p < 3) {
            // gate epilogue: fast activations (MUFU-based)
#pragma unroll
            for (int mt = 0; mt < 2; mt++) {
#pragma unroll
                for (int nt = 0; nt < 4; nt++) {
                    int col = wn * 32 + nt * 8 + tig * 2;
                    float2 bg = *(const float2*)(g_gb + p * HD + col);
#pragma unroll
                    for (int q = 0; q < 4; q++) {
                        float gv = acc[mt][nt][q] + ((q & 1) ? bg.y : bg.x);
                        if (p == 0)      cp[mt][nt][q] = fsig(gv);
                        else if (p == 1) cp[mt][nt][q] = cp[mt][nt][q] * ftanh(gv);
                        else             cp[mt][nt][q] = fsig(gv) * ftanh(cp[mt][nt][q]);
                    }
                }
            }
        } else {
            // conv1-transform epilogue: t = acc * dinv[row] -> gmem fp16
#pragma unroll
            for (int mt = 0; mt < 2; mt++) {
                int row0 = r0 + wm * 32 + mt * 16 + gid;
                int row1 = row0 + 8;
                float dv0 = (row0 < n) ? dinv[row0] : 0.f;
                float dv1 = (row1 < n) ? dinv[row1] : 0.f;
#pragma unroll
                for (int nt = 0; nt < 4; nt++) {
                    int col = wn * 32 + nt * 8 + tig * 2;
                    __half2 v0 = __float22half2_rn(make_float2(acc[mt][nt][0] * dv0, acc[mt][nt][1] * dv0));
                    __half2 v1 = __float22half2_rn(make_float2(acc[mt][nt][2] * dv1, acc[mt][nt][3] * dv1));
                    if (row0 < n) *(uint32_t*)(tout + (size_t)row0 * HD + col) = *(uint32_t*)&v0;
                    if (row1 < n) *(uint32_t*)(tout + (size_t)row1 * HD + col) = *(uint32_t*)&v1;
                }
            }
        }
    }
}

// ================= mma GEMM, full-K resident, single fp16 =================
// MODE 1: t = acc * dinv[row] -> fp16 C16;  MODE 2: out = relu(acc + bias[col]) -> fp32
#define G_A   0           // 128 x 272 = 34816
#define G_B   34816
#define SMEM_G 69632

template <int MODE>
__global__ void __launch_bounds__(256, 2)
mma_gemm(const __half* __restrict__ A, const __half* __restrict__ Bp,
         const float* __restrict__ bias, const float* __restrict__ dinv,
         __half* __restrict__ C16, float* __restrict__ C32, int n) {
    extern __shared__ char sm[];
    uint32_t sbase = smem_u32(sm);

    int tid = threadIdx.x, lane = tid & 31, wid = tid >> 5;
    int gid = lane >> 2, tig = lane & 3;
    int wm = wid & 3, wn = wid >> 2;
    int r0 = blockIdx.x * 128;

    uint32_t aAl = (uint32_t)((wm * 32 + (lane & 15)) * ASTR + ((lane >> 4) << 3) * 2);
    uint32_t aBl = (uint32_t)((wn * 64 + ((lane >> 4) << 3) + (lane & 7)) * ASTR
                              + ((lane >> 3) & 1) * 16);

    float acc[2][8][4];
#pragma unroll
    for (int mt = 0; mt < 2; mt++)
#pragma unroll
        for (int nt = 0; nt < 8; nt++)
#pragma unroll
            for (int q = 0; q < 4; q++) acc[mt][nt][q] = 0.0f;

    for (int i = tid; i < 128 * 16; i += 256) {
        int row = i >> 4, q = i & 15;
        uint4 u = make_uint4(0u, 0u, 0u, 0u);
        if (r0 + row < n)
            u = *(const uint4*)(A + (size_t)(r0 + row) * HD + q * 8);
        *(uint4*)(sm + G_A + row * ASTR + q * 16) = u;
        uint4 h = __ldg((const uint4*)(Bp + (size_t)row * HD + q * 8));
        *(uint4*)(sm + G_B + row * ASTR + q * 16) = h;
    }
    __syncthreads();

#pragma unroll
    for (int ks = 0; ks < 8; ks++) {
        uint32_t ra0[4], ra1[4];
        LDSM4(ra0, sbase + G_A + aAl + ks * 32);
        LDSM4(ra1, sbase + G_A + aAl + 16 * ASTR + ks * 32);
#pragma unroll
        for (int nt2 = 0; nt2 < 4; nt2++) {
            uint32_t rb[4];
            LDSM4(rb, sbase + G_B + aBl + nt2 * 16 * ASTR + ks * 32);
            mma_f16(acc[0][nt2 * 2 + 0], ra0, rb + 0);
            mma_f16(acc[0][nt2 * 2 + 1], ra0, rb + 2);
            mma_f16(acc[1][nt2 * 2 + 0], ra1, rb + 0);
            mma_f16(acc[1][nt2 * 2 + 1], ra1, rb + 2);
        }
    }

#pragma unroll
    for (int mt = 0; mt < 2; mt++) {
        int row0 = r0 + wm * 32 + mt * 16 + gid;
        int row1 = row0 + 8;
        float dv0 = 0.f, dv1 = 0.f;
        if (MODE == 1) {
            dv0 = (row0 < n) ? dinv[row0] : 0.f;
            dv1 = (row1 < n) ? dinv[row1] : 0.f;
        }
#pragma unroll
        for (int nt = 0; nt < 8; nt++) {
            int col = wn * 64 + nt * 8 + tig * 2;
            float d0 = acc[mt][nt][0], d1 = acc[mt][nt][1];
            float d2 = acc[mt][nt][2], d3 = acc[mt][nt][3];
            if (MODE == 1) {
                __half2 v0 = __float22half2_rn(make_float2(d0 * dv0, d1 * dv0));
                __half2 v1 = __float22half2_rn(make_float2(d2 * dv1, d3 * dv1));
                if (row0 < n) *(uint32_t*)(C16 + (size_t)row0 * HD + col) = *(uint32_t*)&v0;
                if (row1 < n) *(uint32_t*)(C16 + (size_t)row1 * HD + col) = *(uint32_t*)&v1;
            } else {
                float b0 = __ldg(bias + col), b1 = __ldg(bias + col + 1);
                if (row0 < n) *(float2*)(C32 + (size_t)row0 * HD + col) =
                    make_float2(fmaxf(d0 + b0, 0.f), fmaxf(d1 + b1, 0.f));
                if (row1 < n) *(float2*)(C32 + (size_t)row1 * HD + col) =
                    make_float2(fmaxf(d2 + b0, 0.f), fmaxf(d3 + b1, 0.f));
            }
        }
    }
}

// ================= CSR aggregation, fp16 in/out, fp32 accum =================
template <bool RELU>
__global__ void aggregate_k(const __half* __restrict__ t2,
                            const float* __restrict__ bias,
                            __half* __restrict__ out, int n) {
    int w = (blockIdx.x * blockDim.x + threadIdx.x) >> 5;
    int lane = threadIdx.x & 31;
    if (w >= n) return;
    const uint2* T = (const uint2*)t2;
    uint2 self = T[(size_t)w * 32 + lane];
    float2 a0 = __half22float2(*(__half2*)&self.x);
    float2 a1 = __half22float2(*(__half2*)&self.y);
    float4 acc = make_float4(a0.x, a0.y, a1.x, a1.y);
    const int* idx = g_csr + g_off[w];
    int cnt = g_deg[w];
    int i = 0;
    for (; i + 7 < cnt; i += 8) {
        int ix[8];
#pragma unroll
        for (int u = 0; u < 8; u++) ix[u] = idx[i + u];
        uint2 v[8];
#pragma unroll
        for (int u = 0; u < 8; u++) v[u] = T[(size_t)ix[u] * 32 + lane];
#pragma unroll
        for (int u = 0; u < 8; u++) {
            float2 f0 = __half22float2(*(__half2*)&v[u].x);
            float2 f1 = __half22float2(*(__half2*)&v[u].y);
            acc.x += f0.x; acc.y += f0.y; acc.z += f1.x; acc.w += f1.y;
        }
    }
    for (; i < cnt; i++) {
        uint2 v = T[(size_t)idx[i] * 32 + lane];
        float2 f0 = __half22float2(*(__half2*)&v.x);
        float2 f1 = __half22float2(*(__half2*)&v.y);
        acc.x += f0.x; acc.y += f0.y; acc.z += f1.x; acc.w += f1.y;
    }
    float dvv = g_dinv[w];
    float4 b4 = ((const float4*)bias)[lane];
    float o0 = acc.x * dvv + b4.x, o1 = acc.y * dvv + b4.y;
    float o2 = acc.z * dvv + b4.z, o3 = acc.w * dvv + b4.w;
    if (RELU) {
        o0 = fmaxf(o0, 0.f); o1 = fmaxf(o1, 0.f);
        o2 = fmaxf(o2, 0.f); o3 = fmaxf(o3, 0.f);
    }
    __half2 h0 = __float22half2_rn(make_float2(o0, o1));
    __half2 h1 = __float22half2_rn(make_float2(o2, o3));
    uint2 o = make_uint2(*(uint32_t*)&h0, *(uint32_t*)&h1);
    ((uint2*)out)[(size_t)w * 32 + lane] = o;
}

// ================= launch =================
extern "C" void kernel_launch(void* const* d_in, const int* in_sizes, int n_in,
                              void* d_out, int out_size) {
    const float* z   = (const float*)d_in[0];
    const int*   ei  = (const int*)d_in[1];
    const float* Wih = (const float*)d_in[2];
    const float* bih = (const float*)d_in[4];
    const float* bhh = (const float*)d_in[5];
    const float* W1  = (const float*)d_in[6];
    const float* b1  = (const float*)d_in[7];
    const float* W2  = (const float*)d_in[8];
    const float* b2  = (const float*)d_in[9];
    const float* W3  = (const float*)d_in[10];
    const float* b3  = (const float*)d_in[11];

    int n = in_sizes[0] / HD;
    int e = in_sizes[1] / 2;
    float* out = (float*)d_out;

    __half *p_tf, *p_sf, *p_wf;
    float *p_dinv;
    cudaGetSymbolAddress((void**)&p_tf, g_tf);
    cudaGetSymbolAddress((void**)&p_sf, g_sf);
    cudaGetSymbolAddress((void**)&p_wf, g_wf);
    cudaGetSymbolAddress((void**)&p_dinv, g_dinv);

    cudaFuncSetAttribute(lstm_fused, cudaFuncAttributeMaxDynamicSharedMemorySize, L_TOT);
    cudaFuncSetAttribute(mma_gemm<1>, cudaFuncAttributeMaxDynamicSharedMemorySize, SMEM_G);
    cudaFuncSetAttribute(mma_gemm<2>, cudaFuncAttributeMaxDynamicSharedMemorySize, SMEM_G);

    int nb = (n + 1023) / 1024;
    // ordering: ncu capture slot (4th launch) = lstm_fused
    prep_zero<<<(n + 255) / 256, 256>>>(Wih, W1, W2, W3, bih, bhh, n);          // 1
    deg_count<<<(e + 255) / 256, 256>>>(ei, e);                                  // 2
    scan_k<<<nb, 1024>>>(n);                                                     // 3 (dinv + off + cur)
    lstm_fused<<<(n + 63) / 64, 256, L_TOT>>>(z, p_dinv, p_tf, n);               // 4 <- profiled
    csr_fill<<<(e + 255) / 256, 256>>>(ei, e);                                   // 5

    dim3 gg((n + 127) / 128);
    // conv1 aggregate + fused relu: s = relu(dinv*(t+sum)+b1)
    aggregate_k<true><<<((size_t)n * 32 + 255) / 256, 256>>>(p_tf, b1, p_sf, n);
    // conv2 transform: t = (s @ W2) * dinv[row]
    mma_gemm<1><<<gg, 256, SMEM_G>>>(p_sf, p_wf + 4 * 16384, nullptr, p_dinv, p_tf, nullptr, n);
    aggregate_k<false><<<((size_t)n * 32 + 255) / 256, 256>>>(p_tf, b2, p_sf, n);
    // final: out = relu(s @ W3^T + b3)
    mma_gemm<2><<<gg, 256, SMEM_G>>>(p_sf, p_wf + 5 * 16384, b3, nullptr, nullptr, out, n);
}